// round 7
// baseline (speedup 1.0000x reference)
#include <cuda_runtime.h>
#include <math.h>
#include <stdint.h>

// ---------------- problem constants (fixed by dataset) ----------------
#define NODES 50000
#define NEDGE 600000
#define ETOT  (NEDGE + NODES)   // edges + self loops
#define FIN   256
#define HID   128
#define NCLS  20
#define NEG_SLOPE 0.2f

#define SCAN_BLK 1024
#define NTILES ((NODES + SCAN_BLK - 1) / SCAN_BLK)   // 49

// ---------------- scratch (static device globals; referenced directly) ----
__device__ __align__(16) float g_h  [(size_t)NODES * HID];  // GEMM outputs
__device__ __align__(16) float g_x2 [(size_t)NODES * HID];  // aggregation outputs
__device__ __align__(16) float g_as [NODES];
__device__ __align__(16) float g_ad [NODES];
__device__ int g_cnt[NODES];
__device__ int g_rowptr[NODES + 1];
__device__ int g_fill[NODES];
__device__ int g_col[ETOT];
__device__ int g_tilesum[NTILES];
__device__ int g_tileoff[NTILES];
__device__ int g_is64;   // 1 if edge_index is int64 in memory, 0 if int32

// ---------------- cp.async helpers ----------------
__device__ __forceinline__ void cp_async16(uint32_t dst, const void* src, int src_bytes) {
    asm volatile("cp.async.cg.shared.global [%0], [%1], 16, %2;"
                 :: "r"(dst), "l"(src), "r"(src_bytes));
}
__device__ __forceinline__ void cp_commit() { asm volatile("cp.async.commit_group;"); }
template <int N>
__device__ __forceinline__ void cp_wait() { asm volatile("cp.async.wait_group %0;" :: "n"(N)); }

__device__ __forceinline__ uint32_t f2tf32(float x) {
    uint32_t r;
    asm("cvt.rna.tf32.f32 %0, %1;" : "=r"(r) : "f"(x));
    return r;
}
__device__ __forceinline__ void mma_tf32(float* d, const uint32_t* a, const uint32_t* b) {
    asm volatile(
        "mma.sync.aligned.m16n8k8.row.col.f32.tf32.tf32.f32 "
        "{%0,%1,%2,%3}, {%4,%5,%6,%7}, {%8,%9}, {%0,%1,%2,%3};"
        : "+f"(d[0]), "+f"(d[1]), "+f"(d[2]), "+f"(d[3])
        : "r"(a[0]), "r"(a[1]), "r"(a[2]), "r"(a[3]), "r"(b[0]), "r"(b[1]));
}

// ---------------- dtype probe: int64 layout => odd 32-bit words all zero ----
__global__ void probe_dtype_k(const unsigned int* __restrict__ ei32) {
    int lane = threadIdx.x;
    int odd_nonzero = 0;
    for (int i = lane; i < 64; i += 32)
        if (ei32[2 * i + 1] != 0u) odd_nonzero = 1;
    #pragma unroll
    for (int o = 16; o; o >>= 1)
        odd_nonzero |= __shfl_xor_sync(0xffffffffu, odd_nonzero, o);
    if (lane == 0) g_is64 = odd_nonzero ? 0 : 1;
}

__device__ __forceinline__ int load_edge(const void* ei, long long idx) {
    int v;
    if (g_is64) v = (int)((const long long*)ei)[idx];
    else        v = ((const int*)ei)[idx];
    return (v < 0) ? 0 : (v >= NODES ? NODES - 1 : v);
}

// ---------------- CSR build ----------------
__global__ void zero_cnt_k() {
    int i = blockIdx.x * blockDim.x + threadIdx.x;
    if (i < NODES) g_cnt[i] = 0;
}

__global__ void count_edges_k(const void* __restrict__ ei) {
    int e = blockIdx.x * blockDim.x + threadIdx.x;
    if (e >= ETOT) return;
    int dst = (e < NEDGE) ? load_edge(ei, (long long)NEDGE + e) : (e - NEDGE);
    atomicAdd(&g_cnt[dst], 1);
}

__global__ void scan_phase1_k() {
    __shared__ int sh[SCAN_BLK];
    int t = threadIdx.x;
    int i = blockIdx.x * SCAN_BLK + t;
    int v = (i < NODES) ? g_cnt[i] : 0;
    sh[t] = v;
    __syncthreads();
    for (int off = 1; off < SCAN_BLK; off <<= 1) {
        int x = 0;
        if (t >= off) x = sh[t - off];
        __syncthreads();
        sh[t] += x;
        __syncthreads();
    }
    if (i < NODES) g_rowptr[i] = sh[t] - v;
    if (t == SCAN_BLK - 1) g_tilesum[blockIdx.x] = sh[t];
}

__global__ void scan_phase2_k() {
    __shared__ int sh[64];
    int t = threadIdx.x;
    int v = (t < NTILES) ? g_tilesum[t] : 0;
    sh[t] = v;
    __syncthreads();
    for (int off = 1; off < 64; off <<= 1) {
        int x = 0;
        if (t >= off) x = sh[t - off];
        __syncthreads();
        sh[t] += x;
        __syncthreads();
    }
    if (t < NTILES) g_tileoff[t] = sh[t] - v;
    if (t == 63) g_rowptr[NODES] = sh[63];
}

__global__ void scan_phase3_k() {
    int i = blockIdx.x * blockDim.x + threadIdx.x;
    if (i >= NODES) return;
    int r = g_rowptr[i] + g_tileoff[i / SCAN_BLK];
    g_rowptr[i] = r;
    g_fill[i]   = r;
}

__global__ void fill_edges_k(const void* __restrict__ ei) {
    int e = blockIdx.x * blockDim.x + threadIdx.x;
    if (e >= ETOT) return;
    int src, dst;
    if (e < NEDGE) {
        src = load_edge(ei, e);
        dst = load_edge(ei, (long long)NEDGE + e);
    } else {
        src = dst = e - NEDGE;
    }
    int p = atomicAdd(&g_fill[dst], 1);
    g_col[p] = src;
}

// ---------------- TF32 tensor-core GEMM ----------------
// g_h[M x 128] = A[M x K] @ B[K x 128] (+bias)(relu); A_EXT: A from param, else g_x2.
#define ASTR 20
#define BSTR 136

template <bool A_EXT, bool BIAS, bool RELU>
__global__ __launch_bounds__(256, 2)
void gemm_tf32_k(const float* __restrict__ Ap, const float* __restrict__ B,
                 const float* __restrict__ bias, int M, int K) {
    const int BM = 128, BN = 128, BK = 16;
    const float* A = A_EXT ? Ap : (const float*)g_x2;
    float* C = g_h;

    __shared__ float As[2][BM][ASTR];
    __shared__ float Bs[2][BK][BSTR];

    const int tid  = threadIdx.x;
    const int lane = tid & 31;
    const int wid  = tid >> 5;
    const int wm   = (wid >> 2) * 64;
    const int wn   = (wid & 3) * 32;
    const int gid  = lane >> 2;
    const int tig  = lane & 3;
    const int block_row = blockIdx.x * BM;

    const int a_row  = tid / 4;
    const int a_col4 = tid % 4;
    const int b_row  = tid / 32;
    const int b_col4 = tid % 32;

    float acc[4][4][4];
    #pragma unroll
    for (int mt = 0; mt < 4; mt++)
        #pragma unroll
        for (int nt = 0; nt < 4; nt++)
            #pragma unroll
            for (int r = 0; r < 4; r++) acc[mt][nt][r] = 0.f;

    auto load_tile = [&](int k0, int s) {
        #pragma unroll
        for (int half = 0; half < 2; half++) {
            int r = a_row + half * 64;
            int grow = block_row + r;
            const float* src = A + (size_t)grow * K + k0 + a_col4 * 4;
            uint32_t dst = (uint32_t)__cvta_generic_to_shared(&As[s][r][a_col4 * 4]);
            cp_async16(dst, src, (grow < M) ? 16 : 0);
        }
        #pragma unroll
        for (int half = 0; half < 2; half++) {
            int r = b_row + half * 8;
            const float* src = B + (size_t)(k0 + r) * BN + b_col4 * 4;
            uint32_t dst = (uint32_t)__cvta_generic_to_shared(&Bs[s][r][b_col4 * 4]);
            cp_async16(dst, src, 16);
        }
    };

    load_tile(0, 0);
    cp_commit();

    int buf = 0;
    for (int k0 = 0; k0 < K; k0 += BK) {
        if (k0 + BK < K) load_tile(k0 + BK, buf ^ 1);
        cp_commit();
        cp_wait<1>();
        __syncthreads();

        #pragma unroll
        for (int ks = 0; ks < BK; ks += 8) {
            uint32_t afr[4][4];
            #pragma unroll
            for (int mt = 0; mt < 4; mt++) {
                int r = wm + mt * 16;
                afr[mt][0] = f2tf32(As[buf][r + gid     ][ks + tig    ]);
                afr[mt][1] = f2tf32(As[buf][r + gid + 8 ][ks + tig    ]);
                afr[mt][2] = f2tf32(As[buf][r + gid     ][ks + tig + 4]);
                afr[mt][3] = f2tf32(As[buf][r + gid + 8 ][ks + tig + 4]);
            }
            uint32_t bfr[4][2];
            #pragma unroll
            for (int nt = 0; nt < 4; nt++) {
                int c = wn + nt * 8 + gid;
                bfr[nt][0] = f2tf32(Bs[buf][ks + tig    ][c]);
                bfr[nt][1] = f2tf32(Bs[buf][ks + tig + 4][c]);
            }
            #pragma unroll
            for (int mt = 0; mt < 4; mt++)
                #pragma unroll
                for (int nt = 0; nt < 4; nt++)
                    mma_tf32(acc[mt][nt], afr[mt], bfr[nt]);
        }
        __syncthreads();
        buf ^= 1;
    }
    cp_wait<0>();

    #pragma unroll
    for (int mt = 0; mt < 4; mt++) {
        #pragma unroll
        for (int nt = 0; nt < 4; nt++) {
            int col = wn + nt * 8 + 2 * tig;
            float b0 = 0.f, b1 = 0.f;
            if (BIAS) { b0 = bias[col]; b1 = bias[col + 1]; }
            #pragma unroll
            for (int half = 0; half < 2; half++) {
                int grow = block_row + wm + mt * 16 + gid + half * 8;
                if (grow >= M) continue;
                float v0 = acc[mt][nt][2 * half + 0] + b0;
                float v1 = acc[mt][nt][2 * half + 1] + b1;
                if (RELU) { v0 = fmaxf(v0, 0.f); v1 = fmaxf(v1, 0.f); }
                float2* dst = reinterpret_cast<float2*>(C + (size_t)grow * BN + col);
                *dst = make_float2(v0, v1);
            }
        }
    }
}

// ---------------- per-node attention dots on g_h -> g_as / g_ad ----------------
__global__ void node_dots_k(const float* __restrict__ a_src, const float* __restrict__ a_dst) {
    int node = blockIdx.x * (blockDim.x >> 5) + (threadIdx.x >> 5);
    if (node >= NODES) return;
    int lane = threadIdx.x & 31;
    float4 hv = reinterpret_cast<const float4*>(g_h + (size_t)node * HID)[lane];
    float4 s4 = reinterpret_cast<const float4*>(a_src)[lane];
    float4 d4 = reinterpret_cast<const float4*>(a_dst)[lane];
    float s = hv.x * s4.x + hv.y * s4.y + hv.z * s4.z + hv.w * s4.w;
    float d = hv.x * d4.x + hv.y * d4.y + hv.z * d4.z + hv.w * d4.w;
    #pragma unroll
    for (int o = 16; o; o >>= 1) {
        s += __shfl_xor_sync(0xffffffffu, s, o);
        d += __shfl_xor_sync(0xffffffffu, d, o);
    }
    if (lane == 0) { g_as[node] = s; g_ad[node] = d; }
}

// ---------------- GAT aggregation: one warp per node, ONLINE softmax (1 pass) ----
template <bool RELU>
__global__ void gat_aggregate_k(const float* __restrict__ bias) {
    int node = blockIdx.x * (blockDim.x >> 5) + (threadIdx.x >> 5);
    if (node >= NODES) return;
    int lane = threadIdx.x & 31;
    int beg = g_rowptr[node], end = g_rowptr[node + 1];
    float adn = g_ad[node];

    float m = -INFINITY;
    float denom = 0.f;
    float4 acc = make_float4(0.f, 0.f, 0.f, 0.f);

    // degree >= 1 always (self loop), so beg < end
    int   s_next = g_col[beg];
    float a_next = g_as[s_next];

    for (int e = beg; e < end; e++) {
        int s = s_next;
        float av = a_next;
        // issue the big row gather as early as possible
        float4 hv = reinterpret_cast<const float4*>(g_h + (size_t)s * HID)[lane];
        if (e + 1 < end) {                   // warp-uniform branch
            s_next = g_col[e + 1];
            a_next = g_as[s_next];
        }
        float l = av + adn;
        l = l > 0.f ? l : NEG_SLOPE * l;
        float w;
        if (l > m) {                          // warp-uniform: l, m broadcast
            float sc = __expf(m - l);         // m=-inf -> sc=0 zeroes empty acc
            m = l;
            denom *= sc;
            acc.x *= sc; acc.y *= sc; acc.z *= sc; acc.w *= sc;
            w = 1.f;
        } else {
            w = __expf(l - m);
        }
        denom += w;
        acc.x = fmaf(w, hv.x, acc.x);
        acc.y = fmaf(w, hv.y, acc.y);
        acc.z = fmaf(w, hv.z, acc.z);
        acc.w = fmaf(w, hv.w, acc.w);
    }

    float inv = 1.f / denom;
    float4 b4 = reinterpret_cast<const float4*>(bias)[lane];
    float4 o4;
    o4.x = acc.x * inv + b4.x;
    o4.y = acc.y * inv + b4.y;
    o4.z = acc.z * inv + b4.z;
    o4.w = acc.w * inv + b4.w;
    if (RELU) {
        o4.x = fmaxf(o4.x, 0.f); o4.y = fmaxf(o4.y, 0.f);
        o4.z = fmaxf(o4.z, 0.f); o4.w = fmaxf(o4.w, 0.f);
    }
    reinterpret_cast<float4*>(g_x2 + (size_t)node * HID)[lane] = o4;
}

// ---------------- final: out = sigmoid(g_h @ Wm2 + bm2), Wm2: [128 x 20] ----------------
__global__ void mlp_out_k(const float* __restrict__ W, const float* __restrict__ b,
                          float* __restrict__ out) {
    __shared__ float Ws[HID * NCLS];
    __shared__ float bs[NCLS];
    for (int i = threadIdx.x; i < HID * NCLS; i += blockDim.x) Ws[i] = W[i];
    if (threadIdx.x < NCLS) bs[threadIdx.x] = b[threadIdx.x];
    __syncthreads();
    int idx = blockIdx.x * blockDim.x + threadIdx.x;
    int row = idx / NCLS, c = idx % NCLS;
    if (row >= NODES) return;
    const float* zr = g_h + (size_t)row * HID;
    float acc = bs[c];
    #pragma unroll 8
    for (int k = 0; k < HID; k++) acc = fmaf(zr[k], Ws[k * NCLS + c], acc);
    out[idx] = 1.f / (1.f + __expf(-acc));
}

// ---------------- launch ----------------
extern "C" void kernel_launch(void* const* d_in, const int* in_sizes, int n_in,
                              void* d_out, int out_size) {
    const float* x    = (const float*)d_in[0];
    const void*  ei   = d_in[1];
    const float* W1   = (const float*)d_in[2];
    const float* as1  = (const float*)d_in[3];
    const float* ad1  = (const float*)d_in[4];
    const float* b1   = (const float*)d_in[5];
    const float* W2   = (const float*)d_in[6];
    const float* as2  = (const float*)d_in[7];
    const float* ad2  = (const float*)d_in[8];
    const float* b2   = (const float*)d_in[9];
    const float* Wm1  = (const float*)d_in[10];
    const float* bm1  = (const float*)d_in[11];
    const float* Wm2  = (const float*)d_in[12];
    const float* bm2  = (const float*)d_in[13];
    float*       out  = (float*)d_out;

    const int gemm_grid  = (NODES + 127) / 128;
    const int warps_grid = (NODES + 7) / 8;
    const int edge_grid  = (ETOT + 255) / 256;
    const int node_grid  = (NODES + 255) / 256;

    probe_dtype_k<<<1, 32>>>((const unsigned int*)ei);
    zero_cnt_k<<<node_grid, 256>>>();
    count_edges_k<<<edge_grid, 256>>>(ei);
    scan_phase1_k<<<NTILES, SCAN_BLK>>>();
    scan_phase2_k<<<1, 64>>>();
    scan_phase3_k<<<node_grid, 256>>>();
    fill_edges_k<<<edge_grid, 256>>>(ei);

    // --- GAT layer 1 ---
    gemm_tf32_k<true, false, false><<<gemm_grid, 256>>>(x, W1, nullptr, NODES, FIN);
    node_dots_k<<<warps_grid, 256>>>(as1, ad1);
    gat_aggregate_k<true><<<warps_grid, 256>>>(b1);

    // --- GAT layer 2 ---
    gemm_tf32_k<false, false, false><<<gemm_grid, 256>>>(nullptr, W2, nullptr, NODES, HID);
    node_dots_k<<<warps_grid, 256>>>(as2, ad2);
    gat_aggregate_k<false><<<warps_grid, 256>>>(b2);

    // --- MLP head ---
    gemm_tf32_k<false, true, true><<<gemm_grid, 256>>>(nullptr, Wm1, bm1, NODES, HID);
    mlp_out_k<<<(NODES * NCLS + 319) / 320, 320>>>(Wm2, bm2, out);
}

// round 8
// speedup vs baseline: 1.0611x; 1.0611x over previous
#include <cuda_runtime.h>
#include <math.h>
#include <stdint.h>

// ---------------- problem constants (fixed by dataset) ----------------
#define NODES 50000
#define NEDGE 600000
#define ETOT  (NEDGE + NODES)   // edges + self loops
#define FIN   256
#define HID   128
#define NCLS  20
#define NEG_SLOPE 0.2f

#define SCAN_BLK 1024
#define NTILES ((NODES + SCAN_BLK - 1) / SCAN_BLK)   // 49

// ---------------- scratch (static device globals; referenced directly) ----
__device__ __align__(16) float g_h  [(size_t)NODES * HID];  // GEMM outputs
__device__ __align__(16) float g_x2 [(size_t)NODES * HID];  // aggregation outputs
__device__ __align__(16) float g_as [NODES];
__device__ __align__(16) float g_ad [NODES];
__device__ int g_cnt[NODES];
__device__ int g_rowptr[NODES + 1];
__device__ int g_fill[NODES];
__device__ int g_col[ETOT];
__device__ int g_tilesum[NTILES];
__device__ int g_tileoff[NTILES];
__device__ int g_is64;   // 1 if edge_index is int64 in memory, 0 if int32

// ---------------- cp.async helpers ----------------
__device__ __forceinline__ void cp_async16(uint32_t dst, const void* src, int src_bytes) {
    asm volatile("cp.async.cg.shared.global [%0], [%1], 16, %2;"
                 :: "r"(dst), "l"(src), "r"(src_bytes));
}
__device__ __forceinline__ void cp_commit() { asm volatile("cp.async.commit_group;"); }
template <int N>
__device__ __forceinline__ void cp_wait() { asm volatile("cp.async.wait_group %0;" :: "n"(N)); }

__device__ __forceinline__ uint32_t f2tf32(float x) {
    uint32_t r;
    asm("cvt.rna.tf32.f32 %0, %1;" : "=r"(r) : "f"(x));
    return r;
}
__device__ __forceinline__ void mma_tf32(float* d, const uint32_t* a, const uint32_t* b) {
    asm volatile(
        "mma.sync.aligned.m16n8k8.row.col.f32.tf32.tf32.f32 "
        "{%0,%1,%2,%3}, {%4,%5,%6,%7}, {%8,%9}, {%0,%1,%2,%3};"
        : "+f"(d[0]), "+f"(d[1]), "+f"(d[2]), "+f"(d[3])
        : "r"(a[0]), "r"(a[1]), "r"(a[2]), "r"(a[3]), "r"(b[0]), "r"(b[1]));
}

// ---------------- dtype probe: int64 layout => odd 32-bit words all zero ----
__global__ void probe_dtype_k(const unsigned int* __restrict__ ei32) {
    int lane = threadIdx.x;
    int odd_nonzero = 0;
    for (int i = lane; i < 64; i += 32)
        if (ei32[2 * i + 1] != 0u) odd_nonzero = 1;
    #pragma unroll
    for (int o = 16; o; o >>= 1)
        odd_nonzero |= __shfl_xor_sync(0xffffffffu, odd_nonzero, o);
    if (lane == 0) g_is64 = odd_nonzero ? 0 : 1;
}

__device__ __forceinline__ int load_edge(const void* ei, long long idx) {
    int v;
    if (g_is64) v = (int)((const long long*)ei)[idx];
    else        v = ((const int*)ei)[idx];
    return (v < 0) ? 0 : (v >= NODES ? NODES - 1 : v);
}

// ---------------- CSR build ----------------
__global__ void zero_cnt_k() {
    int i = blockIdx.x * blockDim.x + threadIdx.x;
    if (i < NODES) g_cnt[i] = 0;
}

__global__ void count_edges_k(const void* __restrict__ ei) {
    int e = blockIdx.x * blockDim.x + threadIdx.x;
    if (e >= ETOT) return;
    int dst = (e < NEDGE) ? load_edge(ei, (long long)NEDGE + e) : (e - NEDGE);
    atomicAdd(&g_cnt[dst], 1);
}

__global__ void scan_phase1_k() {
    __shared__ int sh[SCAN_BLK];
    int t = threadIdx.x;
    int i = blockIdx.x * SCAN_BLK + t;
    int v = (i < NODES) ? g_cnt[i] : 0;
    sh[t] = v;
    __syncthreads();
    for (int off = 1; off < SCAN_BLK; off <<= 1) {
        int x = 0;
        if (t >= off) x = sh[t - off];
        __syncthreads();
        sh[t] += x;
        __syncthreads();
    }
    if (i < NODES) g_rowptr[i] = sh[t] - v;
    if (t == SCAN_BLK - 1) g_tilesum[blockIdx.x] = sh[t];
}

__global__ void scan_phase2_k() {
    __shared__ int sh[64];
    int t = threadIdx.x;
    int v = (t < NTILES) ? g_tilesum[t] : 0;
    sh[t] = v;
    __syncthreads();
    for (int off = 1; off < 64; off <<= 1) {
        int x = 0;
        if (t >= off) x = sh[t - off];
        __syncthreads();
        sh[t] += x;
        __syncthreads();
    }
    if (t < NTILES) g_tileoff[t] = sh[t] - v;
    if (t == 63) g_rowptr[NODES] = sh[63];
}

__global__ void scan_phase3_k() {
    int i = blockIdx.x * blockDim.x + threadIdx.x;
    if (i >= NODES) return;
    int r = g_rowptr[i] + g_tileoff[i / SCAN_BLK];
    g_rowptr[i] = r;
    g_fill[i]   = r;
}

__global__ void fill_edges_k(const void* __restrict__ ei) {
    int e = blockIdx.x * blockDim.x + threadIdx.x;
    if (e >= ETOT) return;
    int src, dst;
    if (e < NEDGE) {
        src = load_edge(ei, e);
        dst = load_edge(ei, (long long)NEDGE + e);
    } else {
        src = dst = e - NEDGE;
    }
    int p = atomicAdd(&g_fill[dst], 1);
    g_col[p] = src;
}

// ---------------- TF32 tensor-core GEMM (+ fused attention dots) ----------------
// g_h[M x 128] = A[M x K] @ B[K x 128] (+bias)(relu); A_EXT: A from param, else g_x2.
// DOTS: also emit g_as[row] = h[row].a_src, g_ad[row] = h[row].a_dst via smem reduction.
#define ASTR 20
#define BSTR 136

template <bool A_EXT, bool BIAS, bool RELU, bool DOTS>
__global__ __launch_bounds__(256, 2)
void gemm_tf32_k(const float* __restrict__ Ap, const float* __restrict__ B,
                 const float* __restrict__ bias,
                 const float* __restrict__ a_src, const float* __restrict__ a_dst,
                 int M, int K) {
    const int BM = 128, BN = 128, BK = 16;
    const float* A = A_EXT ? Ap : (const float*)g_x2;
    float* C = g_h;

    __shared__ float As[2][BM][ASTR];
    __shared__ float Bs[2][BK][BSTR];
    __shared__ float sh_s[BM];
    __shared__ float sh_d[BM];

    const int tid  = threadIdx.x;
    const int lane = tid & 31;
    const int wid  = tid >> 5;
    const int wm   = (wid >> 2) * 64;
    const int wn   = (wid & 3) * 32;
    const int gid  = lane >> 2;
    const int tig  = lane & 3;
    const int block_row = blockIdx.x * BM;

    const int a_row  = tid / 4;
    const int a_col4 = tid % 4;
    const int b_row  = tid / 32;
    const int b_col4 = tid % 32;

    if (DOTS && tid < BM) { sh_s[tid] = 0.f; sh_d[tid] = 0.f; }

    float acc[4][4][4];
    #pragma unroll
    for (int mt = 0; mt < 4; mt++)
        #pragma unroll
        for (int nt = 0; nt < 4; nt++)
            #pragma unroll
            for (int r = 0; r < 4; r++) acc[mt][nt][r] = 0.f;

    auto load_tile = [&](int k0, int s) {
        #pragma unroll
        for (int half = 0; half < 2; half++) {
            int r = a_row + half * 64;
            int grow = block_row + r;
            const float* src = A + (size_t)grow * K + k0 + a_col4 * 4;
            uint32_t dst = (uint32_t)__cvta_generic_to_shared(&As[s][r][a_col4 * 4]);
            cp_async16(dst, src, (grow < M) ? 16 : 0);
        }
        #pragma unroll
        for (int half = 0; half < 2; half++) {
            int r = b_row + half * 8;
            const float* src = B + (size_t)(k0 + r) * BN + b_col4 * 4;
            uint32_t dst = (uint32_t)__cvta_generic_to_shared(&Bs[s][r][b_col4 * 4]);
            cp_async16(dst, src, 16);
        }
    };

    load_tile(0, 0);
    cp_commit();

    int buf = 0;
    for (int k0 = 0; k0 < K; k0 += BK) {
        if (k0 + BK < K) load_tile(k0 + BK, buf ^ 1);
        cp_commit();
        cp_wait<1>();
        __syncthreads();

        #pragma unroll
        for (int ks = 0; ks < BK; ks += 8) {
            uint32_t afr[4][4];
            #pragma unroll
            for (int mt = 0; mt < 4; mt++) {
                int r = wm + mt * 16;
                afr[mt][0] = f2tf32(As[buf][r + gid     ][ks + tig    ]);
                afr[mt][1] = f2tf32(As[buf][r + gid + 8 ][ks + tig    ]);
                afr[mt][2] = f2tf32(As[buf][r + gid     ][ks + tig + 4]);
                afr[mt][3] = f2tf32(As[buf][r + gid + 8 ][ks + tig + 4]);
            }
            uint32_t bfr[4][2];
            #pragma unroll
            for (int nt = 0; nt < 4; nt++) {
                int c = wn + nt * 8 + gid;
                bfr[nt][0] = f2tf32(Bs[buf][ks + tig    ][c]);
                bfr[nt][1] = f2tf32(Bs[buf][ks + tig + 4][c]);
            }
            #pragma unroll
            for (int mt = 0; mt < 4; mt++)
                #pragma unroll
                for (int nt = 0; nt < 4; nt++)
                    mma_tf32(acc[mt][nt], afr[mt], bfr[nt]);
        }
        __syncthreads();
        buf ^= 1;
    }
    cp_wait<0>();

    // per-thread attention-vector values for its 8 columns
    float vs[4][2], vd[4][2];
    if (DOTS) {
        #pragma unroll
        for (int nt = 0; nt < 4; nt++) {
            int col = wn + nt * 8 + 2 * tig;
            vs[nt][0] = a_src[col];     vs[nt][1] = a_src[col + 1];
            vd[nt][0] = a_dst[col];     vd[nt][1] = a_dst[col + 1];
        }
    }

    #pragma unroll
    for (int mt = 0; mt < 4; mt++) {
        #pragma unroll
        for (int half = 0; half < 2; half++) {
            int rloc = wm + mt * 16 + gid + half * 8;
            int grow = block_row + rloc;
            if (grow >= M) continue;
            float ps = 0.f, pd = 0.f;
            #pragma unroll
            for (int nt = 0; nt < 4; nt++) {
                int col = wn + nt * 8 + 2 * tig;
                float v0 = acc[mt][nt][2 * half + 0];
                float v1 = acc[mt][nt][2 * half + 1];
                if (BIAS) { v0 += bias[col]; v1 += bias[col + 1]; }
                if (RELU) { v0 = fmaxf(v0, 0.f); v1 = fmaxf(v1, 0.f); }
                if (DOTS) {
                    ps = fmaf(v0, vs[nt][0], fmaf(v1, vs[nt][1], ps));
                    pd = fmaf(v0, vd[nt][0], fmaf(v1, vd[nt][1], pd));
                }
                float2* dst = reinterpret_cast<float2*>(C + (size_t)grow * BN + col);
                *dst = make_float2(v0, v1);
            }
            if (DOTS) {
                atomicAdd(&sh_s[rloc], ps);
                atomicAdd(&sh_d[rloc], pd);
            }
        }
    }

    if (DOTS) {
        __syncthreads();
        if (tid < BM) {
            int grow = block_row + tid;
            if (grow < M) { g_as[grow] = sh_s[tid]; g_ad[grow] = sh_d[tid]; }
        }
    }
}

// ---------------- GAT aggregation: one warp per node, two-pass (R6 version) ----
template <bool RELU>
__global__ void gat_aggregate_k(const float* __restrict__ bias) {
    int node = blockIdx.x * (blockDim.x >> 5) + (threadIdx.x >> 5);
    if (node >= NODES) return;
    int lane = threadIdx.x & 31;
    int beg = g_rowptr[node], end = g_rowptr[node + 1];
    float adn = g_ad[node];

    // pass 1: segment max (lanes split edges)
    float m = -INFINITY;
    for (int e = beg + lane; e < end; e += 32) {
        float l = g_as[g_col[e]] + adn;
        l = l > 0.f ? l : NEG_SLOPE * l;
        m = fmaxf(m, l);
    }
    #pragma unroll
    for (int o = 16; o; o >>= 1) m = fmaxf(m, __shfl_xor_sync(0xffffffffu, m, o));

    // pass 2: exp-weighted accumulate (lanes own 4 columns each)
    float4 acc = make_float4(0.f, 0.f, 0.f, 0.f);
    float denom = 0.f;
    for (int e = beg; e < end; e++) {
        int s = g_col[e];
        float l = g_as[s] + adn;
        l = l > 0.f ? l : NEG_SLOPE * l;
        float w = __expf(l - m);
        denom += w;
        float4 hv = reinterpret_cast<const float4*>(g_h + (size_t)s * HID)[lane];
        acc.x = fmaf(w, hv.x, acc.x);
        acc.y = fmaf(w, hv.y, acc.y);
        acc.z = fmaf(w, hv.z, acc.z);
        acc.w = fmaf(w, hv.w, acc.w);
    }
    float inv = 1.f / denom;
    float4 b4 = reinterpret_cast<const float4*>(bias)[lane];
    float4 o4;
    o4.x = acc.x * inv + b4.x;
    o4.y = acc.y * inv + b4.y;
    o4.z = acc.z * inv + b4.z;
    o4.w = acc.w * inv + b4.w;
    if (RELU) {
        o4.x = fmaxf(o4.x, 0.f); o4.y = fmaxf(o4.y, 0.f);
        o4.z = fmaxf(o4.z, 0.f); o4.w = fmaxf(o4.w, 0.f);
    }
    reinterpret_cast<float4*>(g_x2 + (size_t)node * HID)[lane] = o4;
}

// ---------------- final: out = sigmoid(g_h @ Wm2 + bm2), Wm2: [128 x 20] ----------------
__global__ void mlp_out_k(const float* __restrict__ W, const float* __restrict__ b,
                          float* __restrict__ out) {
    __shared__ float Ws[HID * NCLS];
    __shared__ float bs[NCLS];
    for (int i = threadIdx.x; i < HID * NCLS; i += blockDim.x) Ws[i] = W[i];
    if (threadIdx.x < NCLS) bs[threadIdx.x] = b[threadIdx.x];
    __syncthreads();
    int idx = blockIdx.x * blockDim.x + threadIdx.x;
    int row = idx / NCLS, c = idx % NCLS;
    if (row >= NODES) return;
    const float* zr = g_h + (size_t)row * HID;
    float acc = bs[c];
    #pragma unroll 8
    for (int k = 0; k < HID; k++) acc = fmaf(zr[k], Ws[k * NCLS + c], acc);
    out[idx] = 1.f / (1.f + __expf(-acc));
}

// ---------------- launch ----------------
extern "C" void kernel_launch(void* const* d_in, const int* in_sizes, int n_in,
                              void* d_out, int out_size) {
    const float* x    = (const float*)d_in[0];
    const void*  ei   = d_in[1];
    const float* W1   = (const float*)d_in[2];
    const float* as1  = (const float*)d_in[3];
    const float* ad1  = (const float*)d_in[4];
    const float* b1   = (const float*)d_in[5];
    const float* W2   = (const float*)d_in[6];
    const float* as2  = (const float*)d_in[7];
    const float* ad2  = (const float*)d_in[8];
    const float* b2   = (const float*)d_in[9];
    const float* Wm1  = (const float*)d_in[10];
    const float* bm1  = (const float*)d_in[11];
    const float* Wm2  = (const float*)d_in[12];
    const float* bm2  = (const float*)d_in[13];
    float*       out  = (float*)d_out;

    const int gemm_grid  = (NODES + 127) / 128;
    const int warps_grid = (NODES + 7) / 8;
    const int edge_grid  = (ETOT + 255) / 256;
    const int node_grid  = (NODES + 255) / 256;

    probe_dtype_k<<<1, 32>>>((const unsigned int*)ei);
    zero_cnt_k<<<node_grid, 256>>>();
    count_edges_k<<<edge_grid, 256>>>(ei);
    scan_phase1_k<<<NTILES, SCAN_BLK>>>();
    scan_phase2_k<<<1, 64>>>();
    scan_phase3_k<<<node_grid, 256>>>();
    fill_edges_k<<<edge_grid, 256>>>(ei);

    // --- GAT layer 1 (GEMM + fused dots) ---
    gemm_tf32_k<true, false, false, true><<<gemm_grid, 256>>>(x, W1, nullptr, as1, ad1, NODES, FIN);
    gat_aggregate_k<true><<<warps_grid, 256>>>(b1);

    // --- GAT layer 2 (GEMM + fused dots) ---
    gemm_tf32_k<false, false, false, true><<<gemm_grid, 256>>>(nullptr, W2, nullptr, as2, ad2, NODES, HID);
    gat_aggregate_k<false><<<warps_grid, 256>>>(b2);

    // --- MLP head ---
    gemm_tf32_k<false, true, true, false><<<gemm_grid, 256>>>(nullptr, Wm1, bm1, nullptr, nullptr, NODES, HID);
    mlp_out_k<<<(NODES * NCLS + 319) / 320, 320>>>(Wm2, bm2, out);
}

// round 10
// speedup vs baseline: 1.1305x; 1.0654x over previous
#include <cuda_runtime.h>
#include <cuda_fp16.h>
#include <math.h>
#include <stdint.h>

// ---------------- problem constants (fixed by dataset) ----------------
#define NODES 50000
#define NEDGE 600000
#define ETOT  (NEDGE + NODES)   // edges + self loops
#define FIN   256
#define HID   128
#define NCLS  20
#define NEG_SLOPE 0.2f

#define SCAN_BLK 1024
#define NTILES ((NODES + SCAN_BLK - 1) / SCAN_BLK)   // 49

// ---------------- scratch (static device globals; referenced directly) ----
__device__ __align__(16) float  g_h  [(size_t)NODES * HID];  // f32 GEMM out (MLP head)
__device__ __align__(16) __half g_h16[(size_t)NODES * HID];  // fp16 GEMM out (GAT layers)
__device__ __align__(16) float  g_x2 [(size_t)NODES * HID];  // aggregation outputs
__device__ __align__(16) float  g_as [NODES];
__device__ __align__(16) float  g_ad [NODES];
__device__ int g_cnt[NODES];
__device__ int g_rowptr[NODES + 1];
__device__ int g_fill[NODES];
__device__ int g_col[ETOT];
__device__ int g_tilesum[NTILES];
__device__ int g_tileoff[NTILES];
__device__ int g_is64;

// ---------------- cp.async helpers ----------------
__device__ __forceinline__ void cp_async16(uint32_t dst, const void* src, int src_bytes) {
    asm volatile("cp.async.cg.shared.global [%0], [%1], 16, %2;"
                 :: "r"(dst), "l"(src), "r"(src_bytes));
}
__device__ __forceinline__ void cp_commit() { asm volatile("cp.async.commit_group;"); }
template <int N>
__device__ __forceinline__ void cp_wait() { asm volatile("cp.async.wait_group %0;" :: "n"(N)); }

__device__ __forceinline__ uint32_t f2tf32(float x) {
    uint32_t r;
    asm("cvt.rna.tf32.f32 %0, %1;" : "=r"(r) : "f"(x));
    return r;
}
__device__ __forceinline__ void mma_tf32(float* d, const uint32_t* a, const uint32_t* b) {
    asm volatile(
        "mma.sync.aligned.m16n8k8.row.col.f32.tf32.tf32.f32 "
        "{%0,%1,%2,%3}, {%4,%5,%6,%7}, {%8,%9}, {%0,%1,%2,%3};"
        : "+f"(d[0]), "+f"(d[1]), "+f"(d[2]), "+f"(d[3])
        : "r"(a[0]), "r"(a[1]), "r"(a[2]), "r"(a[3]), "r"(b[0]), "r"(b[1]));
}

// ---------------- dtype probe ----------------
__global__ void probe_dtype_k(const unsigned int* __restrict__ ei32) {
    int lane = threadIdx.x;
    int odd_nonzero = 0;
    for (int i = lane; i < 64; i += 32)
        if (ei32[2 * i + 1] != 0u) odd_nonzero = 1;
    #pragma unroll
    for (int o = 16; o; o >>= 1)
        odd_nonzero |= __shfl_xor_sync(0xffffffffu, odd_nonzero, o);
    if (lane == 0) g_is64 = odd_nonzero ? 0 : 1;
}

__device__ __forceinline__ int load_edge(const void* ei, long long idx) {
    int v;
    if (g_is64) v = (int)((const long long*)ei)[idx];
    else        v = ((const int*)ei)[idx];
    return (v < 0) ? 0 : (v >= NODES ? NODES - 1 : v);
}

// ---------------- CSR build ----------------
__global__ void zero_cnt_k() {
    int i = blockIdx.x * blockDim.x + threadIdx.x;
    if (i < NODES) g_cnt[i] = 0;
}

__global__ void count_edges_k(const void* __restrict__ ei) {
    int e = blockIdx.x * blockDim.x + threadIdx.x;
    if (e >= ETOT) return;
    int dst = (e < NEDGE) ? load_edge(ei, (long long)NEDGE + e) : (e - NEDGE);
    atomicAdd(&g_cnt[dst], 1);
}

__global__ void scan_phase1_k() {
    __shared__ int sh[SCAN_BLK];
    int t = threadIdx.x;
    int i = blockIdx.x * SCAN_BLK + t;
    int v = (i < NODES) ? g_cnt[i] : 0;
    sh[t] = v;
    __syncthreads();
    for (int off = 1; off < SCAN_BLK; off <<= 1) {
        int x = 0;
        if (t >= off) x = sh[t - off];
        __syncthreads();
        sh[t] += x;
        __syncthreads();
    }
    if (i < NODES) g_rowptr[i] = sh[t] - v;
    if (t == SCAN_BLK - 1) g_tilesum[blockIdx.x] = sh[t];
}

__global__ void scan_phase2_k() {
    __shared__ int sh[64];
    int t = threadIdx.x;
    int v = (t < NTILES) ? g_tilesum[t] : 0;
    sh[t] = v;
    __syncthreads();
    for (int off = 1; off < 64; off <<= 1) {
        int x = 0;
        if (t >= off) x = sh[t - off];
        __syncthreads();
        sh[t] += x;
        __syncthreads();
    }
    if (t < NTILES) g_tileoff[t] = sh[t] - v;
    if (t == 63) g_rowptr[NODES] = sh[63];
}

__global__ void scan_phase3_k() {
    int i = blockIdx.x * blockDim.x + threadIdx.x;
    if (i >= NODES) return;
    int r = g_rowptr[i] + g_tileoff[i / SCAN_BLK];
    g_rowptr[i] = r;
    g_fill[i]   = r;
}

__global__ void fill_edges_k(const void* __restrict__ ei) {
    int e = blockIdx.x * blockDim.x + threadIdx.x;
    if (e >= ETOT) return;
    int src, dst;
    if (e < NEDGE) {
        src = load_edge(ei, e);
        dst = load_edge(ei, (long long)NEDGE + e);
    } else {
        src = dst = e - NEDGE;
    }
    int p = atomicAdd(&g_fill[dst], 1);
    g_col[p] = src;
}

// ---------------- TF32 tensor-core GEMM (+ fused attention dots) ----------------
// H16: C -> g_h16 (half). else C -> g_h (f32).
// DOTS: also emit g_as/g_ad via smem reduction.
#define ASTR 20
#define BSTR 136

template <bool A_EXT, bool BIAS, bool RELU, bool DOTS, bool H16>
__global__ __launch_bounds__(256, 2)
void gemm_tf32_k(const float* __restrict__ Ap, const float* __restrict__ B,
                 const float* __restrict__ bias,
                 const float* __restrict__ a_src, const float* __restrict__ a_dst,
                 int M, int K) {
    const int BM = 128, BN = 128, BK = 16;
    const float* A = A_EXT ? Ap : (const float*)g_x2;

    __shared__ float As[2][BM][ASTR];
    __shared__ float Bs[2][BK][BSTR];
    __shared__ float sh_s[BM];
    __shared__ float sh_d[BM];

    const int tid  = threadIdx.x;
    const int lane = tid & 31;
    const int wid  = tid >> 5;
    const int wm   = (wid >> 2) * 64;
    const int wn   = (wid & 3) * 32;
    const int gid  = lane >> 2;
    const int tig  = lane & 3;
    const int block_row = blockIdx.x * BM;

    const int a_row  = tid / 4;
    const int a_col4 = tid % 4;
    const int b_row  = tid / 32;
    const int b_col4 = tid % 32;

    if (DOTS && tid < BM) { sh_s[tid] = 0.f; sh_d[tid] = 0.f; }

    float acc[4][4][4];
    #pragma unroll
    for (int mt = 0; mt < 4; mt++)
        #pragma unroll
        for (int nt = 0; nt < 4; nt++)
            #pragma unroll
            for (int r = 0; r < 4; r++) acc[mt][nt][r] = 0.f;

    auto load_tile = [&](int k0, int s) {
        #pragma unroll
        for (int half = 0; half < 2; half++) {
            int r = a_row + half * 64;
            int grow = block_row + r;
            const float* src = A + (size_t)grow * K + k0 + a_col4 * 4;
            uint32_t dst = (uint32_t)__cvta_generic_to_shared(&As[s][r][a_col4 * 4]);
            cp_async16(dst, src, (grow < M) ? 16 : 0);
        }
        #pragma unroll
        for (int half = 0; half < 2; half++) {
            int r = b_row + half * 8;
            const float* src = B + (size_t)(k0 + r) * BN + b_col4 * 4;
            uint32_t dst = (uint32_t)__cvta_generic_to_shared(&Bs[s][r][b_col4 * 4]);
            cp_async16(dst, src, 16);
        }
    };

    load_tile(0, 0);
    cp_commit();

    int buf = 0;
    for (int k0 = 0; k0 < K; k0 += BK) {
        if (k0 + BK < K) load_tile(k0 + BK, buf ^ 1);
        cp_commit();
        cp_wait<1>();
        __syncthreads();

        #pragma unroll
        for (int ks = 0; ks < BK; ks += 8) {
            uint32_t afr[4][4];
            #pragma unroll
            for (int mt = 0; mt < 4; mt++) {
                int r = wm + mt * 16;
                afr[mt][0] = f2tf32(As[buf][r + gid     ][ks + tig    ]);
                afr[mt][1] = f2tf32(As[buf][r + gid + 8 ][ks + tig    ]);
                afr[mt][2] = f2tf32(As[buf][r + gid     ][ks + tig + 4]);
                afr[mt][3] = f2tf32(As[buf][r + gid + 8 ][ks + tig + 4]);
            }
            uint32_t bfr[4][2];
            #pragma unroll
            for (int nt = 0; nt < 4; nt++) {
                int c = wn + nt * 8 + gid;
                bfr[nt][0] = f2tf32(Bs[buf][ks + tig    ][c]);
                bfr[nt][1] = f2tf32(Bs[buf][ks + tig + 4][c]);
            }
            #pragma unroll
            for (int mt = 0; mt < 4; mt++)
                #pragma unroll
                for (int nt = 0; nt < 4; nt++)
                    mma_tf32(acc[mt][nt], afr[mt], bfr[nt]);
        }
        __syncthreads();
        buf ^= 1;
    }
    cp_wait<0>();

    float vs[4][2], vd[4][2];
    if (DOTS) {
        #pragma unroll
        for (int nt = 0; nt < 4; nt++) {
            int col = wn + nt * 8 + 2 * tig;
            vs[nt][0] = a_src[col];     vs[nt][1] = a_src[col + 1];
            vd[nt][0] = a_dst[col];     vd[nt][1] = a_dst[col + 1];
        }
    }

    #pragma unroll
    for (int mt = 0; mt < 4; mt++) {
        #pragma unroll
        for (int half = 0; half < 2; half++) {
            int rloc = wm + mt * 16 + gid + half * 8;
            int grow = block_row + rloc;
            if (grow >= M) continue;
            float ps = 0.f, pd = 0.f;
            #pragma unroll
            for (int nt = 0; nt < 4; nt++) {
                int col = wn + nt * 8 + 2 * tig;
                float v0 = acc[mt][nt][2 * half + 0];
                float v1 = acc[mt][nt][2 * half + 1];
                if (BIAS) { v0 += bias[col]; v1 += bias[col + 1]; }
                if (RELU) { v0 = fmaxf(v0, 0.f); v1 = fmaxf(v1, 0.f); }
                if (DOTS) {
                    ps = fmaf(v0, vs[nt][0], fmaf(v1, vs[nt][1], ps));
                    pd = fmaf(v0, vd[nt][0], fmaf(v1, vd[nt][1], pd));
                }
                if (H16) {
                    __half2 hv = __floats2half2_rn(v0, v1);
                    *reinterpret_cast<__half2*>(g_h16 + (size_t)grow * BN + col) = hv;
                } else {
                    float2* dst = reinterpret_cast<float2*>(g_h + (size_t)grow * BN + col);
                    *dst = make_float2(v0, v1);
                }
            }
            if (DOTS) {
                atomicAdd(&sh_s[rloc], ps);
                atomicAdd(&sh_d[rloc], pd);
            }
        }
    }

    if (DOTS) {
        __syncthreads();
        if (tid < BM) {
            int grow = block_row + tid;
            if (grow < M) { g_as[grow] = sh_s[tid]; g_ad[grow] = sh_d[tid]; }
        }
    }
}

// ---------------- GAT aggregation: one warp per node, two-pass, fp16 gather ----
template <bool RELU>
__global__ void gat_aggregate_k(const float* __restrict__ bias) {
    int node = blockIdx.x * (blockDim.x >> 5) + (threadIdx.x >> 5);
    if (node >= NODES) return;
    int lane = threadIdx.x & 31;
    int beg = g_rowptr[node], end = g_rowptr[node + 1];
    float adn = g_ad[node];

    // pass 1: segment max (lanes split edges)
    float m = -INFINITY;
    for (int e = beg + lane; e < end; e += 32) {
        float l = g_as[g_col[e]] + adn;
        l = l > 0.f ? l : NEG_SLOPE * l;
        m = fmaxf(m, l);
    }
    #pragma unroll
    for (int o = 16; o; o >>= 1) m = fmaxf(m, __shfl_xor_sync(0xffffffffu, m, o));

    // pass 2: exp-weighted accumulate; lane owns 4 cols (8 bytes fp16)
    float4 acc = make_float4(0.f, 0.f, 0.f, 0.f);
    float denom = 0.f;
    for (int e = beg; e < end; e++) {
        int s = g_col[e];
        float l = g_as[s] + adn;
        l = l > 0.f ? l : NEG_SLOPE * l;
        float w = __expf(l - m);
        denom += w;
        uint2 raw = reinterpret_cast<const uint2*>(g_h16 + (size_t)s * HID)[lane];
        __half2 p0 = *reinterpret_cast<__half2*>(&raw.x);
        __half2 p1 = *reinterpret_cast<__half2*>(&raw.y);
        float2 f0 = __half22float2(p0);
        float2 f1 = __half22float2(p1);
        acc.x = fmaf(w, f0.x, acc.x);
        acc.y = fmaf(w, f0.y, acc.y);
        acc.z = fmaf(w, f1.x, acc.z);
        acc.w = fmaf(w, f1.y, acc.w);
    }
    float inv = 1.f / denom;
    float4 b4 = reinterpret_cast<const float4*>(bias)[lane];
    float4 o4;
    o4.x = acc.x * inv + b4.x;
    o4.y = acc.y * inv + b4.y;
    o4.z = acc.z * inv + b4.z;
    o4.w = acc.w * inv + b4.w;
    if (RELU) {
        o4.x = fmaxf(o4.x, 0.f); o4.y = fmaxf(o4.y, 0.f);
        o4.z = fmaxf(o4.z, 0.f); o4.w = fmaxf(o4.w, 0.f);
    }
    reinterpret_cast<float4*>(g_x2 + (size_t)node * HID)[lane] = o4;
}

// ---------------- final: out = sigmoid(g_h @ Wm2 + bm2), vectorized ----------------
#define MLP_ROWS 64
__global__ __launch_bounds__(256)
void mlp_out_k(const float* __restrict__ W, const float* __restrict__ b,
               float* __restrict__ out) {
    __shared__ float Wst[NCLS][HID + 4];   // transposed W: [c][k]
    __shared__ float bs[NCLS];
    __shared__ __align__(16) float hs[MLP_ROWS][HID];

    int tid = threadIdx.x;
    for (int i = tid; i < HID * NCLS; i += blockDim.x)
        Wst[i % NCLS][i / NCLS] = W[i];
    if (tid < NCLS) bs[tid] = b[tid];

    int row0 = blockIdx.x * MLP_ROWS;
    // cooperative row load: 64 rows x 32 float4 = 2048 float4
    const float4* src = reinterpret_cast<const float4*>(g_h + (size_t)row0 * HID);
    float4* dst4 = reinterpret_cast<float4*>(&hs[0][0]);
    int n4 = min(MLP_ROWS, NODES - row0) * (HID / 4);
    for (int i = tid; i < n4; i += blockDim.x) dst4[i] = src[i];
    __syncthreads();

    int nout = min(MLP_ROWS, NODES - row0) * NCLS;
    for (int o = tid; o < nout; o += blockDim.x) {
        int rl = o / NCLS, c = o % NCLS;
        const float4* zr = reinterpret_cast<const float4*>(&hs[rl][0]);
        const float4* wc = reinterpret_cast<const float4*>(&Wst[c][0]);
        float acc = bs[c];
        #pragma unroll
        for (int k = 0; k < HID / 4; k++) {
            float4 z = zr[k];
            float4 w = wc[k];
            acc = fmaf(z.x, w.x, acc);
            acc = fmaf(z.y, w.y, acc);
            acc = fmaf(z.z, w.z, acc);
            acc = fmaf(z.w, w.w, acc);
        }
        out[(size_t)(row0 + rl) * NCLS + c] = 1.f / (1.f + __expf(-acc));
    }
}

// ---------------- launch ----------------
extern "C" void kernel_launch(void* const* d_in, const int* in_sizes, int n_in,
                              void* d_out, int out_size) {
    const float* x    = (const float*)d_in[0];
    const void*  ei   = d_in[1];
    const float* W1   = (const float*)d_in[2];
    const float* as1  = (const float*)d_in[3];
    const float* ad1  = (const float*)d_in[4];
    const float* b1   = (const float*)d_in[5];
    const float* W2   = (const float*)d_in[6];
    const float* as2  = (const float*)d_in[7];
    const float* ad2  = (const float*)d_in[8];
    const float* b2   = (const float*)d_in[9];
    const float* Wm1  = (const float*)d_in[10];
    const float* bm1  = (const float*)d_in[11];
    const float* Wm2  = (const float*)d_in[12];
    const float* bm2  = (const float*)d_in[13];
    float*       out  = (float*)d_out;

    const int gemm_grid  = (NODES + 127) / 128;
    const int warps_grid = (NODES + 7) / 8;
    const int edge_grid  = (ETOT + 255) / 256;
    const int node_grid  = (NODES + 255) / 256;

    probe_dtype_k<<<1, 32>>>((const unsigned int*)ei);
    zero_cnt_k<<<node_grid, 256>>>();
    count_edges_k<<<edge_grid, 256>>>(ei);
    scan_phase1_k<<<NTILES, SCAN_BLK>>>();
    scan_phase2_k<<<1, 64>>>();
    scan_phase3_k<<<node_grid, 256>>>();
    fill_edges_k<<<edge_grid, 256>>>(ei);

    // --- GAT layer 1 (GEMM + fused dots, fp16 h) ---
    gemm_tf32_k<true, false, false, true, true><<<gemm_grid, 256>>>(x, W1, nullptr, as1, ad1, NODES, FIN);
    gat_aggregate_k<true><<<warps_grid, 256>>>(b1);

    // --- GAT layer 2 (GEMM + fused dots, fp16 h) ---
    gemm_tf32_k<false, false, false, true, true><<<gemm_grid, 256>>>(nullptr, W2, nullptr, as2, ad2, NODES, HID);
    gat_aggregate_k<false><<<warps_grid, 256>>>(b2);

    // --- MLP head (f32 h) ---
    gemm_tf32_k<false, true, true, false, false><<<gemm_grid, 256>>>(nullptr, Wm1, bm1, nullptr, nullptr, NODES, HID);
    mlp_out_k<<<(NODES + MLP_ROWS - 1) / MLP_ROWS, 256>>>(Wm2, bm2, out);
}

// round 11
// speedup vs baseline: 1.1632x; 1.0288x over previous
#include <cuda_runtime.h>
#include <cuda_fp16.h>
#include <math.h>
#include <stdint.h>

// ---------------- problem constants (fixed by dataset) ----------------
#define NODES 50000
#define NEDGE 600000
#define ETOT  (NEDGE + NODES)   // edges + self loops
#define FIN   256
#define HID   128
#define NCLS  20
#define NEG_SLOPE 0.2f

#define SCAN_BLK 1024
#define NTILES ((NODES + SCAN_BLK - 1) / SCAN_BLK)   // 49

// ---------------- scratch (static device globals; referenced directly) ----
__device__ __align__(16) float  g_h  [(size_t)NODES * HID];  // f32 GEMM out (MLP head)
__device__ __align__(16) __half g_h16[(size_t)NODES * HID];  // fp16 GEMM out (GAT layers)
__device__ __align__(16) float  g_x2 [(size_t)NODES * HID];  // aggregation outputs
__device__ __align__(16) float  g_as [NODES];
__device__ __align__(16) float  g_ad [NODES];
__device__ int g_cnt[NODES];
__device__ int g_rowptr[NODES + 1];
__device__ int g_fill[NODES];
__device__ int g_col[ETOT];
__device__ int g_tilesum[NTILES];
__device__ int g_tileoff[NTILES];
__device__ int g_is64;
__device__ unsigned g_asmax[2];   // order-encoded global max of g_as, per GAT layer

// ---------------- order-preserving float<->uint encoding (for atomicMax) ----
__device__ __forceinline__ unsigned enc_ord(float f) {
    unsigned u = __float_as_uint(f);
    return (u & 0x80000000u) ? ~u : (u | 0x80000000u);
}
__device__ __forceinline__ float dec_ord(unsigned k) {
    return (k & 0x80000000u) ? __uint_as_float(k & 0x7fffffffu)
                             : __uint_as_float(~k);
}

// ---------------- cp.async helpers ----------------
__device__ __forceinline__ void cp_async16(uint32_t dst, const void* src, int src_bytes) {
    asm volatile("cp.async.cg.shared.global [%0], [%1], 16, %2;"
                 :: "r"(dst), "l"(src), "r"(src_bytes));
}
__device__ __forceinline__ void cp_commit() { asm volatile("cp.async.commit_group;"); }
template <int N>
__device__ __forceinline__ void cp_wait() { asm volatile("cp.async.wait_group %0;" :: "n"(N)); }

__device__ __forceinline__ uint32_t f2tf32(float x) {
    uint32_t r;
    asm("cvt.rna.tf32.f32 %0, %1;" : "=r"(r) : "f"(x));
    return r;
}
__device__ __forceinline__ void mma_tf32(float* d, const uint32_t* a, const uint32_t* b) {
    asm volatile(
        "mma.sync.aligned.m16n8k8.row.col.f32.tf32.tf32.f32 "
        "{%0,%1,%2,%3}, {%4,%5,%6,%7}, {%8,%9}, {%0,%1,%2,%3};"
        : "+f"(d[0]), "+f"(d[1]), "+f"(d[2]), "+f"(d[3])
        : "r"(a[0]), "r"(a[1]), "r"(a[2]), "r"(a[3]), "r"(b[0]), "r"(b[1]));
}

__device__ __forceinline__ int load_edge(const void* ei, long long idx) {
    int v;
    if (g_is64) v = (int)((const long long*)ei)[idx];
    else        v = ((const int*)ei)[idx];
    return (v < 0) ? 0 : (v >= NODES ? NODES - 1 : v);
}

// ---------------- init: zero counts + dtype probe + asmax reset ----------------
__global__ void init_k(const unsigned int* __restrict__ ei32) {
    int i = blockIdx.x * blockDim.x + threadIdx.x;
    if (i < NODES) g_cnt[i] = 0;
    if (blockIdx.x == 0) {
        if (threadIdx.x < 32) {
            int lane = threadIdx.x;
            int odd_nonzero = 0;
            for (int j = lane; j < 64; j += 32)
                if (ei32[2 * j + 1] != 0u) odd_nonzero = 1;
            #pragma unroll
            for (int o = 16; o; o >>= 1)
                odd_nonzero |= __shfl_xor_sync(0xffffffffu, odd_nonzero, o);
            if (lane == 0) g_is64 = odd_nonzero ? 0 : 1;
        } else if (threadIdx.x == 32) {
            g_asmax[0] = 0u;   // below enc(-inf): safe floor
            g_asmax[1] = 0u;
        }
    }
}

__global__ void count_edges_k(const void* __restrict__ ei) {
    int e = blockIdx.x * blockDim.x + threadIdx.x;
    if (e >= ETOT) return;
    int dst = (e < NEDGE) ? load_edge(ei, (long long)NEDGE + e) : (e - NEDGE);
    atomicAdd(&g_cnt[dst], 1);
}

__global__ void scan_phase1_k() {
    __shared__ int sh[SCAN_BLK];
    int t = threadIdx.x;
    int i = blockIdx.x * SCAN_BLK + t;
    int v = (i < NODES) ? g_cnt[i] : 0;
    sh[t] = v;
    __syncthreads();
    for (int off = 1; off < SCAN_BLK; off <<= 1) {
        int x = 0;
        if (t >= off) x = sh[t - off];
        __syncthreads();
        sh[t] += x;
        __syncthreads();
    }
    if (i < NODES) g_rowptr[i] = sh[t] - v;
    if (t == SCAN_BLK - 1) g_tilesum[blockIdx.x] = sh[t];
}

__global__ void scan_phase2_k() {
    __shared__ int sh[64];
    int t = threadIdx.x;
    int v = (t < NTILES) ? g_tilesum[t] : 0;
    sh[t] = v;
    __syncthreads();
    for (int off = 1; off < 64; off <<= 1) {
        int x = 0;
        if (t >= off) x = sh[t - off];
        __syncthreads();
        sh[t] += x;
        __syncthreads();
    }
    if (t < NTILES) g_tileoff[t] = sh[t] - v;
    if (t == 63) g_rowptr[NODES] = sh[63];
}

__global__ void scan_phase3_k() {
    int i = blockIdx.x * blockDim.x + threadIdx.x;
    if (i >= NODES) return;
    int r = g_rowptr[i] + g_tileoff[i / SCAN_BLK];
    g_rowptr[i] = r;
    g_fill[i]   = r;
}

__global__ void fill_edges_k(const void* __restrict__ ei) {
    int e = blockIdx.x * blockDim.x + threadIdx.x;
    if (e >= ETOT) return;
    int src, dst;
    if (e < NEDGE) {
        src = load_edge(ei, e);
        dst = load_edge(ei, (long long)NEDGE + e);
    } else {
        src = dst = e - NEDGE;
    }
    int p = atomicAdd(&g_fill[dst], 1);
    g_col[p] = src;
}

// ---------------- TF32 tensor-core GEMM (+ fused attention dots + asmax) -------
// H16: C -> g_h16 (half). else C -> g_h (f32).
// DOTS: also emit g_as/g_ad via smem reduction, and atomicMax of g_as into g_asmax[layer].
#define ASTR 20
#define BSTR 136

template <bool A_EXT, bool BIAS, bool RELU, bool DOTS, bool H16>
__global__ __launch_bounds__(256, 2)
void gemm_tf32_k(const float* __restrict__ Ap, const float* __restrict__ B,
                 const float* __restrict__ bias,
                 const float* __restrict__ a_src, const float* __restrict__ a_dst,
                 int M, int K, int layer) {
    const int BM = 128, BN = 128, BK = 16;
    const float* A = A_EXT ? Ap : (const float*)g_x2;

    __shared__ float As[2][BM][ASTR];
    __shared__ float Bs[2][BK][BSTR];
    __shared__ float sh_s[BM];
    __shared__ float sh_d[BM];

    const int tid  = threadIdx.x;
    const int lane = tid & 31;
    const int wid  = tid >> 5;
    const int wm   = (wid >> 2) * 64;
    const int wn   = (wid & 3) * 32;
    const int gid  = lane >> 2;
    const int tig  = lane & 3;
    const int block_row = blockIdx.x * BM;

    const int a_row  = tid / 4;
    const int a_col4 = tid % 4;
    const int b_row  = tid / 32;
    const int b_col4 = tid % 32;

    if (DOTS && tid < BM) { sh_s[tid] = 0.f; sh_d[tid] = 0.f; }

    float acc[4][4][4];
    #pragma unroll
    for (int mt = 0; mt < 4; mt++)
        #pragma unroll
        for (int nt = 0; nt < 4; nt++)
            #pragma unroll
            for (int r = 0; r < 4; r++) acc[mt][nt][r] = 0.f;

    auto load_tile = [&](int k0, int s) {
        #pragma unroll
        for (int half = 0; half < 2; half++) {
            int r = a_row + half * 64;
            int grow = block_row + r;
            const float* src = A + (size_t)grow * K + k0 + a_col4 * 4;
            uint32_t dst = (uint32_t)__cvta_generic_to_shared(&As[s][r][a_col4 * 4]);
            cp_async16(dst, src, (grow < M) ? 16 : 0);
        }
        #pragma unroll
        for (int half = 0; half < 2; half++) {
            int r = b_row + half * 8;
            const float* src = B + (size_t)(k0 + r) * BN + b_col4 * 4;
            uint32_t dst = (uint32_t)__cvta_generic_to_shared(&Bs[s][r][b_col4 * 4]);
            cp_async16(dst, src, 16);
        }
    };

    load_tile(0, 0);
    cp_commit();

    int buf = 0;
    for (int k0 = 0; k0 < K; k0 += BK) {
        if (k0 + BK < K) load_tile(k0 + BK, buf ^ 1);
        cp_commit();
        cp_wait<1>();
        __syncthreads();

        #pragma unroll
        for (int ks = 0; ks < BK; ks += 8) {
            uint32_t afr[4][4];
            #pragma unroll
            for (int mt = 0; mt < 4; mt++) {
                int r = wm + mt * 16;
                afr[mt][0] = f2tf32(As[buf][r + gid     ][ks + tig    ]);
                afr[mt][1] = f2tf32(As[buf][r + gid + 8 ][ks + tig    ]);
                afr[mt][2] = f2tf32(As[buf][r + gid     ][ks + tig + 4]);
                afr[mt][3] = f2tf32(As[buf][r + gid + 8 ][ks + tig + 4]);
            }
            uint32_t bfr[4][2];
            #pragma unroll
            for (int nt = 0; nt < 4; nt++) {
                int c = wn + nt * 8 + gid;
                bfr[nt][0] = f2tf32(Bs[buf][ks + tig    ][c]);
                bfr[nt][1] = f2tf32(Bs[buf][ks + tig + 4][c]);
            }
            #pragma unroll
            for (int mt = 0; mt < 4; mt++)
                #pragma unroll
                for (int nt = 0; nt < 4; nt++)
                    mma_tf32(acc[mt][nt], afr[mt], bfr[nt]);
        }
        __syncthreads();
        buf ^= 1;
    }
    cp_wait<0>();

    float vs[4][2], vd[4][2];
    if (DOTS) {
        #pragma unroll
        for (int nt = 0; nt < 4; nt++) {
            int col = wn + nt * 8 + 2 * tig;
            vs[nt][0] = a_src[col];     vs[nt][1] = a_src[col + 1];
            vd[nt][0] = a_dst[col];     vd[nt][1] = a_dst[col + 1];
        }
    }

    #pragma unroll
    for (int mt = 0; mt < 4; mt++) {
        #pragma unroll
        for (int half = 0; half < 2; half++) {
            int rloc = wm + mt * 16 + gid + half * 8;
            int grow = block_row + rloc;
            if (grow >= M) continue;
            float ps = 0.f, pd = 0.f;
            #pragma unroll
            for (int nt = 0; nt < 4; nt++) {
                int col = wn + nt * 8 + 2 * tig;
                float v0 = acc[mt][nt][2 * half + 0];
                float v1 = acc[mt][nt][2 * half + 1];
                if (BIAS) { v0 += bias[col]; v1 += bias[col + 1]; }
                if (RELU) { v0 = fmaxf(v0, 0.f); v1 = fmaxf(v1, 0.f); }
                if (DOTS) {
                    ps = fmaf(v0, vs[nt][0], fmaf(v1, vs[nt][1], ps));
                    pd = fmaf(v0, vd[nt][0], fmaf(v1, vd[nt][1], pd));
                }
                if (H16) {
                    __half2 hv = __floats2half2_rn(v0, v1);
                    *reinterpret_cast<__half2*>(g_h16 + (size_t)grow * BN + col) = hv;
                } else {
                    float2* dst = reinterpret_cast<float2*>(g_h + (size_t)grow * BN + col);
                    *dst = make_float2(v0, v1);
                }
            }
            if (DOTS) {
                atomicAdd(&sh_s[rloc], ps);
                atomicAdd(&sh_d[rloc], pd);
            }
        }
    }

    if (DOTS) {
        __syncthreads();
        if (tid < BM) {
            int grow = block_row + tid;
            float sv = -INFINITY;
            if (grow < M) {
                sv = sh_s[tid];
                g_as[grow] = sv;
                g_ad[grow] = sh_d[tid];
            }
            // per-warp max of g_as contribution -> global asmax
            #pragma unroll
            for (int o = 16; o; o >>= 1)
                sv = fmaxf(sv, __shfl_xor_sync(0xffffffffu, sv, o));
            if ((tid & 31) == 0)
                atomicMax(&g_asmax[layer], enc_ord(sv));
        }
    }
}

// ---------------- GAT aggregation: warp/node, single pass w/ global-max bound ----
template <bool RELU>
__global__ void gat_aggregate_k(const float* __restrict__ bias, int layer) {
    int node = blockIdx.x * (blockDim.x >> 5) + (threadIdx.x >> 5);
    if (node >= NODES) return;
    int lane = threadIdx.x & 31;
    int beg = g_rowptr[node], end = g_rowptr[node + 1];
    float adn = g_ad[node];

    // stabilizer: m = leaky(AS_MAX + adn) >= max over this node's edges (leaky monotone)
    float m = dec_ord(g_asmax[layer]) + adn;
    m = m > 0.f ? m : NEG_SLOPE * m;

    float4 acc = make_float4(0.f, 0.f, 0.f, 0.f);
    float denom = 0.f;
    for (int e = beg; e < end; e++) {
        int s = g_col[e];
        float l = g_as[s] + adn;
        l = l > 0.f ? l : NEG_SLOPE * l;
        float w = __expf(l - m);
        denom += w;
        uint2 raw = reinterpret_cast<const uint2*>(g_h16 + (size_t)s * HID)[lane];
        __half2 p0 = *reinterpret_cast<__half2*>(&raw.x);
        __half2 p1 = *reinterpret_cast<__half2*>(&raw.y);
        float2 f0 = __half22float2(p0);
        float2 f1 = __half22float2(p1);
        acc.x = fmaf(w, f0.x, acc.x);
        acc.y = fmaf(w, f0.y, acc.y);
        acc.z = fmaf(w, f1.x, acc.z);
        acc.w = fmaf(w, f1.y, acc.w);
    }
    float inv = 1.f / denom;
    float4 b4 = reinterpret_cast<const float4*>(bias)[lane];
    float4 o4;
    o4.x = acc.x * inv + b4.x;
    o4.y = acc.y * inv + b4.y;
    o4.z = acc.z * inv + b4.z;
    o4.w = acc.w * inv + b4.w;
    if (RELU) {
        o4.x = fmaxf(o4.x, 0.f); o4.y = fmaxf(o4.y, 0.f);
        o4.z = fmaxf(o4.z, 0.f); o4.w = fmaxf(o4.w, 0.f);
    }
    reinterpret_cast<float4*>(g_x2 + (size_t)node * HID)[lane] = o4;
}

// ---------------- final: out = sigmoid(g_h @ Wm2 + bm2), vectorized ----------------
#define MLP_ROWS 64
__global__ __launch_bounds__(256)
void mlp_out_k(const float* __restrict__ W, const float* __restrict__ b,
               float* __restrict__ out) {
    __shared__ float Wst[NCLS][HID + 4];   // transposed W: [c][k]
    __shared__ float bs[NCLS];
    __shared__ __align__(16) float hs[MLP_ROWS][HID];

    int tid = threadIdx.x;
    for (int i = tid; i < HID * NCLS; i += blockDim.x)
        Wst[i % NCLS][i / NCLS] = W[i];
    if (tid < NCLS) bs[tid] = b[tid];

    int row0 = blockIdx.x * MLP_ROWS;
    const float4* src = reinterpret_cast<const float4*>(g_h + (size_t)row0 * HID);
    float4* dst4 = reinterpret_cast<float4*>(&hs[0][0]);
    int n4 = min(MLP_ROWS, NODES - row0) * (HID / 4);
    for (int i = tid; i < n4; i += blockDim.x) dst4[i] = src[i];
    __syncthreads();

    int nout = min(MLP_ROWS, NODES - row0) * NCLS;
    for (int o = tid; o < nout; o += blockDim.x) {
        int rl = o / NCLS, c = o % NCLS;
        const float4* zr = reinterpret_cast<const float4*>(&hs[rl][0]);
        const float4* wc = reinterpret_cast<const float4*>(&Wst[c][0]);
        float acc = bs[c];
        #pragma unroll
        for (int k = 0; k < HID / 4; k++) {
            float4 z = zr[k];
            float4 w = wc[k];
            acc = fmaf(z.x, w.x, acc);
            acc = fmaf(z.y, w.y, acc);
            acc = fmaf(z.z, w.z, acc);
            acc = fmaf(z.w, w.w, acc);
        }
        out[(size_t)(row0 + rl) * NCLS + c] = 1.f / (1.f + __expf(-acc));
    }
}

// ---------------- launch ----------------
extern "C" void kernel_launch(void* const* d_in, const int* in_sizes, int n_in,
                              void* d_out, int out_size) {
    const float* x    = (const float*)d_in[0];
    const void*  ei   = d_in[1];
    const float* W1   = (const float*)d_in[2];
    const float* as1  = (const float*)d_in[3];
    const float* ad1  = (const float*)d_in[4];
    const float* b1   = (const float*)d_in[5];
    const float* W2   = (const float*)d_in[6];
    const float* as2  = (const float*)d_in[7];
    const float* ad2  = (const float*)d_in[8];
    const float* b2   = (const float*)d_in[9];
    const float* Wm1  = (const float*)d_in[10];
    const float* bm1  = (const float*)d_in[11];
    const float* Wm2  = (const float*)d_in[12];
    const float* bm2  = (const float*)d_in[13];
    float*       out  = (float*)d_out;

    const int gemm_grid  = (NODES + 127) / 128;
    const int warps_grid = (NODES + 7) / 8;
    const int edge_grid  = (ETOT + 255) / 256;
    const int node_grid  = (NODES + 255) / 256;

    init_k<<<node_grid, 256>>>((const unsigned int*)ei);
    count_edges_k<<<edge_grid, 256>>>(ei);
    scan_phase1_k<<<NTILES, SCAN_BLK>>>();
    scan_phase2_k<<<1, 64>>>();
    scan_phase3_k<<<node_grid, 256>>>();
    fill_edges_k<<<edge_grid, 256>>>(ei);

    // --- GAT layer 1 (GEMM + fused dots/asmax, fp16 h) ---
    gemm_tf32_k<true, false, false, true, true><<<gemm_grid, 256>>>(x, W1, nullptr, as1, ad1, NODES, FIN, 0);
    gat_aggregate_k<true><<<warps_grid, 256>>>(b1, 0);

    // --- GAT layer 2 (GEMM + fused dots/asmax, fp16 h) ---
    gemm_tf32_k<false, false, false, true, true><<<gemm_grid, 256>>>(nullptr, W2, nullptr, as2, ad2, NODES, HID, 1);
    gat_aggregate_k<false><<<warps_grid, 256>>>(b2, 1);

    // --- MLP head (f32 h) ---
    gemm_tf32_k<false, true, true, false, false><<<gemm_grid, 256>>>(nullptr, Wm1, bm1, nullptr, nullptr, NODES, HID, 0);
    mlp_out_k<<<(NODES + MLP_ROWS - 1) / MLP_ROWS, 256>>>(Wm2, bm2, out);
}

// round 12
// speedup vs baseline: 1.1761x; 1.0111x over previous
#include <cuda_runtime.h>
#include <cuda_fp16.h>
#include <math.h>
#include <stdint.h>

// ---------------- problem constants (fixed by dataset) ----------------
#define NODES 50000
#define NEDGE 600000
#define ETOT  (NEDGE + NODES)   // edges + self loops
#define FIN   256
#define HID   128
#define NCLS  20
#define NEG_SLOPE 0.2f

#define SCAN_BLK 1024
#define NTILES ((NODES + SCAN_BLK - 1) / SCAN_BLK)   // 49

// ---------------- scratch (static device globals; referenced directly) ----
// Invariants maintained across launches (all deterministic):
//  - g_cnt is all-zero at launch entry (zero-init at load; scan_phase1 re-zeroes)
//  - g_asmax is monotone-stable under atomicMax of identical per-run values
__device__ __align__(16) float  g_h  [(size_t)NODES * HID];  // f32 GEMM out (MLP head)
__device__ __align__(16) __half g_h16[(size_t)NODES * HID];  // fp16 GEMM out (GAT layers)
__device__ __align__(16) float  g_x2 [(size_t)NODES * HID];  // aggregation outputs
__device__ __align__(16) float  g_as [NODES];
__device__ __align__(16) float  g_ad [NODES];
__device__ int g_cnt[NODES];
__device__ int g_rowptr[NODES + 1];   // LOCAL exclusive scan per 1024-tile; [NODES]=total
__device__ int g_fill[NODES];         // local cursors for fill
__device__ int g_col[ETOT];
__device__ int g_tilesum[NTILES];
__device__ int g_tileoff[NTILES];
__device__ unsigned g_asmax[2];       // order-encoded global max of g_as, per GAT layer

// ---------------- order-preserving float<->uint encoding (for atomicMax) ----
__device__ __forceinline__ unsigned enc_ord(float f) {
    unsigned u = __float_as_uint(f);
    return (u & 0x80000000u) ? ~u : (u | 0x80000000u);
}
__device__ __forceinline__ float dec_ord(unsigned k) {
    return (k & 0x80000000u) ? __uint_as_float(k & 0x7fffffffu)
                             : __uint_as_float(~k);
}

// ---------------- cp.async helpers ----------------
__device__ __forceinline__ void cp_async16(uint32_t dst, const void* src, int src_bytes) {
    asm volatile("cp.async.cg.shared.global [%0], [%1], 16, %2;"
                 :: "r"(dst), "l"(src), "r"(src_bytes));
}
__device__ __forceinline__ void cp_commit() { asm volatile("cp.async.commit_group;"); }
template <int N>
__device__ __forceinline__ void cp_wait() { asm volatile("cp.async.wait_group %0;" :: "n"(N)); }

__device__ __forceinline__ uint32_t f2tf32(float x) {
    uint32_t r;
    asm("cvt.rna.tf32.f32 %0, %1;" : "=r"(r) : "f"(x));
    return r;
}
__device__ __forceinline__ void mma_tf32(float* d, const uint32_t* a, const uint32_t* b) {
    asm volatile(
        "mma.sync.aligned.m16n8k8.row.col.f32.tf32.tf32.f32 "
        "{%0,%1,%2,%3}, {%4,%5,%6,%7}, {%8,%9}, {%0,%1,%2,%3};"
        : "+f"(d[0]), "+f"(d[1]), "+f"(d[2]), "+f"(d[3])
        : "r"(a[0]), "r"(a[1]), "r"(a[2]), "r"(a[3]), "r"(b[0]), "r"(b[1]));
}

// per-block dtype probe: int64 layout => odd 32-bit words of first 4 ids all zero
__device__ __forceinline__ int probe_is64_block(const void* ei) {
    __shared__ int s_is64;
    if (threadIdx.x == 0) {
        const unsigned* p = (const unsigned*)ei;
        s_is64 = ((p[1] | p[3] | p[5] | p[7]) == 0u) ? 1 : 0;
    }
    __syncthreads();
    return s_is64;
}

__device__ __forceinline__ int load_edge_i(const void* ei, long long idx, int is64) {
    int v;
    if (is64) v = (int)((const long long*)ei)[idx];
    else      v = ((const int*)ei)[idx];
    return (v < 0) ? 0 : (v >= NODES ? NODES - 1 : v);
}

// ---------------- CSR build ----------------
__global__ void count_edges_k(const void* __restrict__ ei) {
    int is64 = probe_is64_block(ei);
    int e = blockIdx.x * blockDim.x + threadIdx.x;
    if (e >= ETOT) return;
    int dst = (e < NEDGE) ? load_edge_i(ei, (long long)NEDGE + e, is64) : (e - NEDGE);
    atomicAdd(&g_cnt[dst], 1);
}

// local exclusive scan per 1024-tile; zero g_cnt after reading; init local cursors
__global__ void scan_phase1_k() {
    __shared__ int sh[SCAN_BLK];
    int t = threadIdx.x;
    int i = blockIdx.x * SCAN_BLK + t;
    int v = (i < NODES) ? g_cnt[i] : 0;
    sh[t] = v;
    __syncthreads();
    for (int off = 1; off < SCAN_BLK; off <<= 1) {
        int x = 0;
        if (t >= off) x = sh[t - off];
        __syncthreads();
        sh[t] += x;
        __syncthreads();
    }
    if (i < NODES) {
        int loc = sh[t] - v;       // local exclusive
        g_rowptr[i] = loc;
        g_fill[i]   = loc;
        g_cnt[i]    = 0;           // restore all-zero invariant for next launch
    }
    if (t == SCAN_BLK - 1) g_tilesum[blockIdx.x] = sh[t];
}

__global__ void scan_phase2_k() {
    __shared__ int sh[64];
    int t = threadIdx.x;
    int v = (t < NTILES) ? g_tilesum[t] : 0;
    sh[t] = v;
    __syncthreads();
    for (int off = 1; off < 64; off <<= 1) {
        int x = 0;
        if (t >= off) x = sh[t - off];
        __syncthreads();
        sh[t] += x;
        __syncthreads();
    }
    if (t < NTILES) g_tileoff[t] = sh[t] - v;
    if (t == 63) g_rowptr[NODES] = sh[63];   // absolute total
}

__global__ void fill_edges_k(const void* __restrict__ ei) {
    int is64 = probe_is64_block(ei);
    int e = blockIdx.x * blockDim.x + threadIdx.x;
    if (e >= ETOT) return;
    int src, dst;
    if (e < NEDGE) {
        src = load_edge_i(ei, e, is64);
        dst = load_edge_i(ei, (long long)NEDGE + e, is64);
    } else {
        src = dst = e - NEDGE;
    }
    int p = atomicAdd(&g_fill[dst], 1) + g_tileoff[dst >> 10];
    g_col[p] = src;
}

// ---------------- TF32 tensor-core GEMM (+ fused attention dots + asmax) -------
#define ASTR 20
#define BSTR 136

template <bool A_EXT, bool BIAS, bool RELU, bool DOTS, bool H16>
__global__ __launch_bounds__(256, 2)
void gemm_tf32_k(const float* __restrict__ Ap, const float* __restrict__ B,
                 const float* __restrict__ bias,
                 const float* __restrict__ a_src, const float* __restrict__ a_dst,
                 int M, int K, int layer) {
    const int BM = 128, BN = 128, BK = 16;
    const float* A = A_EXT ? Ap : (const float*)g_x2;

    __shared__ float As[2][BM][ASTR];
    __shared__ float Bs[2][BK][BSTR];
    __shared__ float sh_s[BM];
    __shared__ float sh_d[BM];

    const int tid  = threadIdx.x;
    const int lane = tid & 31;
    const int wid  = tid >> 5;
    const int wm   = (wid >> 2) * 64;
    const int wn   = (wid & 3) * 32;
    const int gid  = lane >> 2;
    const int tig  = lane & 3;
    const int block_row = blockIdx.x * BM;

    const int a_row  = tid / 4;
    const int a_col4 = tid % 4;
    const int b_row  = tid / 32;
    const int b_col4 = tid % 32;

    if (DOTS && tid < BM) { sh_s[tid] = 0.f; sh_d[tid] = 0.f; }

    float acc[4][4][4];
    #pragma unroll
    for (int mt = 0; mt < 4; mt++)
        #pragma unroll
        for (int nt = 0; nt < 4; nt++)
            #pragma unroll
            for (int r = 0; r < 4; r++) acc[mt][nt][r] = 0.f;

    auto load_tile = [&](int k0, int s) {
        #pragma unroll
        for (int half = 0; half < 2; half++) {
            int r = a_row + half * 64;
            int grow = block_row + r;
            const float* src = A + (size_t)grow * K + k0 + a_col4 * 4;
            uint32_t dst = (uint32_t)__cvta_generic_to_shared(&As[s][r][a_col4 * 4]);
            cp_async16(dst, src, (grow < M) ? 16 : 0);
        }
        #pragma unroll
        for (int half = 0; half < 2; half++) {
            int r = b_row + half * 8;
            const float* src = B + (size_t)(k0 + r) * BN + b_col4 * 4;
            uint32_t dst = (uint32_t)__cvta_generic_to_shared(&Bs[s][r][b_col4 * 4]);
            cp_async16(dst, src, 16);
        }
    };

    load_tile(0, 0);
    cp_commit();

    int buf = 0;
    for (int k0 = 0; k0 < K; k0 += BK) {
        if (k0 + BK < K) load_tile(k0 + BK, buf ^ 1);
        cp_commit();
        cp_wait<1>();
        __syncthreads();

        #pragma unroll
        for (int ks = 0; ks < BK; ks += 8) {
            uint32_t afr[4][4];
            #pragma unroll
            for (int mt = 0; mt < 4; mt++) {
                int r = wm + mt * 16;
                afr[mt][0] = f2tf32(As[buf][r + gid     ][ks + tig    ]);
                afr[mt][1] = f2tf32(As[buf][r + gid + 8 ][ks + tig    ]);
                afr[mt][2] = f2tf32(As[buf][r + gid     ][ks + tig + 4]);
                afr[mt][3] = f2tf32(As[buf][r + gid + 8 ][ks + tig + 4]);
            }
            uint32_t bfr[4][2];
            #pragma unroll
            for (int nt = 0; nt < 4; nt++) {
                int c = wn + nt * 8 + gid;
                bfr[nt][0] = f2tf32(Bs[buf][ks + tig    ][c]);
                bfr[nt][1] = f2tf32(Bs[buf][ks + tig + 4][c]);
            }
            #pragma unroll
            for (int mt = 0; mt < 4; mt++)
                #pragma unroll
                for (int nt = 0; nt < 4; nt++)
                    mma_tf32(acc[mt][nt], afr[mt], bfr[nt]);
        }
        __syncthreads();
        buf ^= 1;
    }
    cp_wait<0>();

    float vs[4][2], vd[4][2];
    if (DOTS) {
        #pragma unroll
        for (int nt = 0; nt < 4; nt++) {
            int col = wn + nt * 8 + 2 * tig;
            vs[nt][0] = a_src[col];     vs[nt][1] = a_src[col + 1];
            vd[nt][0] = a_dst[col];     vd[nt][1] = a_dst[col + 1];
        }
    }

    #pragma unroll
    for (int mt = 0; mt < 4; mt++) {
        #pragma unroll
        for (int half = 0; half < 2; half++) {
            int rloc = wm + mt * 16 + gid + half * 8;
            int grow = block_row + rloc;
            if (grow >= M) continue;
            float ps = 0.f, pd = 0.f;
            #pragma unroll
            for (int nt = 0; nt < 4; nt++) {
                int col = wn + nt * 8 + 2 * tig;
                float v0 = acc[mt][nt][2 * half + 0];
                float v1 = acc[mt][nt][2 * half + 1];
                if (BIAS) { v0 += bias[col]; v1 += bias[col + 1]; }
                if (RELU) { v0 = fmaxf(v0, 0.f); v1 = fmaxf(v1, 0.f); }
                if (DOTS) {
                    ps = fmaf(v0, vs[nt][0], fmaf(v1, vs[nt][1], ps));
                    pd = fmaf(v0, vd[nt][0], fmaf(v1, vd[nt][1], pd));
                }
                if (H16) {
                    __half2 hv = __floats2half2_rn(v0, v1);
                    *reinterpret_cast<__half2*>(g_h16 + (size_t)grow * BN + col) = hv;
                } else {
                    float2* dst = reinterpret_cast<float2*>(g_h + (size_t)grow * BN + col);
                    *dst = make_float2(v0, v1);
                }
            }
            if (DOTS) {
                atomicAdd(&sh_s[rloc], ps);
                atomicAdd(&sh_d[rloc], pd);
            }
        }
    }

    if (DOTS) {
        __syncthreads();
        if (tid < BM) {
            int grow = block_row + tid;
            float sv = -INFINITY;
            if (grow < M) {
                sv = sh_s[tid];
                g_as[grow] = sv;
                g_ad[grow] = sh_d[tid];
            }
            #pragma unroll
            for (int o = 16; o; o >>= 1)
                sv = fmaxf(sv, __shfl_xor_sync(0xffffffffu, sv, o));
            if ((tid & 31) == 0)
                atomicMax(&g_asmax[layer], enc_ord(sv));
        }
    }
}

// ---------------- GAT aggregation: warp/node, single pass w/ global-max bound ----
template <bool RELU>
__global__ void gat_aggregate_k(const float* __restrict__ bias, int layer) {
    int node = blockIdx.x * (blockDim.x >> 5) + (threadIdx.x >> 5);
    if (node >= NODES) return;
    int lane = threadIdx.x & 31;
    // local scan + tile offset -> absolute positions
    int beg = g_rowptr[node] + g_tileoff[node >> 10];
    int end;
    if (node + 1 < NODES) end = g_rowptr[node + 1] + g_tileoff[(node + 1) >> 10];
    else                  end = g_rowptr[NODES];
    float adn = g_ad[node];

    // stabilizer: m = leaky(AS_MAX + adn) >= node max (leaky monotone, softmax shift-inv)
    float m = dec_ord(g_asmax[layer]) + adn;
    m = m > 0.f ? m : NEG_SLOPE * m;

    float4 acc = make_float4(0.f, 0.f, 0.f, 0.f);
    float denom = 0.f;
    #pragma unroll 2
    for (int e = beg; e < end; e++) {
        int s = g_col[e];
        float l = g_as[s] + adn;
        l = l > 0.f ? l : NEG_SLOPE * l;
        float w = __expf(l - m);
        denom += w;
        uint2 raw = reinterpret_cast<const uint2*>(g_h16 + (size_t)s * HID)[lane];
        __half2 p0 = *reinterpret_cast<__half2*>(&raw.x);
        __half2 p1 = *reinterpret_cast<__half2*>(&raw.y);
        float2 f0 = __half22float2(p0);
        float2 f1 = __half22float2(p1);
        acc.x = fmaf(w, f0.x, acc.x);
        acc.y = fmaf(w, f0.y, acc.y);
        acc.z = fmaf(w, f1.x, acc.z);
        acc.w = fmaf(w, f1.y, acc.w);
    }
    float inv = 1.f / denom;
    float4 b4 = reinterpret_cast<const float4*>(bias)[lane];
    float4 o4;
    o4.x = acc.x * inv + b4.x;
    o4.y = acc.y * inv + b4.y;
    o4.z = acc.z * inv + b4.z;
    o4.w = acc.w * inv + b4.w;
    if (RELU) {
        o4.x = fmaxf(o4.x, 0.f); o4.y = fmaxf(o4.y, 0.f);
        o4.z = fmaxf(o4.z, 0.f); o4.w = fmaxf(o4.w, 0.f);
    }
    reinterpret_cast<float4*>(g_x2 + (size_t)node * HID)[lane] = o4;
}

// ---------------- final: out = sigmoid(g_h @ Wm2 + bm2), vectorized ----------------
#define MLP_ROWS 64
__global__ __launch_bounds__(256)
void mlp_out_k(const float* __restrict__ W, const float* __restrict__ b,
               float* __restrict__ out) {
    __shared__ float Wst[NCLS][HID + 4];
    __shared__ float bs[NCLS];
    __shared__ __align__(16) float hs[MLP_ROWS][HID];

    int tid = threadIdx.x;
    for (int i = tid; i < HID * NCLS; i += blockDim.x)
        Wst[i % NCLS][i / NCLS] = W[i];
    if (tid < NCLS) bs[tid] = b[tid];

    int row0 = blockIdx.x * MLP_ROWS;
    const float4* src = reinterpret_cast<const float4*>(g_h + (size_t)row0 * HID);
    float4* dst4 = reinterpret_cast<float4*>(&hs[0][0]);
    int n4 = min(MLP_ROWS, NODES - row0) * (HID / 4);
    for (int i = tid; i < n4; i += blockDim.x) dst4[i] = src[i];
    __syncthreads();

    int nout = min(MLP_ROWS, NODES - row0) * NCLS;
    for (int o = tid; o < nout; o += blockDim.x) {
        int rl = o / NCLS, c = o % NCLS;
        const float4* zr = reinterpret_cast<const float4*>(&hs[rl][0]);
        const float4* wc = reinterpret_cast<const float4*>(&Wst[c][0]);
        float acc = bs[c];
        #pragma unroll
        for (int k = 0; k < HID / 4; k++) {
            float4 z = zr[k];
            float4 w = wc[k];
            acc = fmaf(z.x, w.x, acc);
            acc = fmaf(z.y, w.y, acc);
            acc = fmaf(z.z, w.z, acc);
            acc = fmaf(z.w, w.w, acc);
        }
        out[(size_t)(row0 + rl) * NCLS + c] = 1.f / (1.f + __expf(-acc));
    }
}

// ---------------- launch ----------------
extern "C" void kernel_launch(void* const* d_in, const int* in_sizes, int n_in,
                              void* d_out, int out_size) {
    const float* x    = (const float*)d_in[0];
    const void*  ei   = d_in[1];
    const float* W1   = (const float*)d_in[2];
    const float* as1  = (const float*)d_in[3];
    const float* ad1  = (const float*)d_in[4];
    const float* b1   = (const float*)d_in[5];
    const float* W2   = (const float*)d_in[6];
    const float* as2  = (const float*)d_in[7];
    const float* ad2  = (const float*)d_in[8];
    const float* b2   = (const float*)d_in[9];
    const float* Wm1  = (const float*)d_in[10];
    const float* bm1  = (const float*)d_in[11];
    const float* Wm2  = (const float*)d_in[12];
    const float* bm2  = (const float*)d_in[13];
    float*       out  = (float*)d_out;

    const int gemm_grid  = (NODES + 127) / 128;
    const int warps_grid = (NODES + 7) / 8;
    const int edge_grid  = (ETOT + 255) / 256;

    // --- CSR build (4 kernels) ---
    count_edges_k<<<edge_grid, 256>>>(ei);
    scan_phase1_k<<<NTILES, SCAN_BLK>>>();
    scan_phase2_k<<<1, 64>>>();
    fill_edges_k<<<edge_grid, 256>>>(ei);

    // --- GAT layer 1 (GEMM + fused dots/asmax, fp16 h) ---
    gemm_tf32_k<true, false, false, true, true><<<gemm_grid, 256>>>(x, W1, nullptr, as1, ad1, NODES, FIN, 0);
    gat_aggregate_k<true><<<warps_grid, 256>>>(b1, 0);

    // --- GAT layer 2 (GEMM + fused dots/asmax, fp16 h) ---
    gemm_tf32_k<false, false, false, true, true><<<gemm_grid, 256>>>(nullptr, W2, nullptr, as2, ad2, NODES, HID, 1);
    gat_aggregate_k<false><<<warps_grid, 256>>>(b2, 1);

    // --- MLP head (f32 h) ---
    gemm_tf32_k<false, true, true, false, false><<<gemm_grid, 256>>>(nullptr, Wm1, bm1, nullptr, nullptr, NODES, HID, 0);
    mlp_out_k<<<(NODES + MLP_ROWS - 1) / MLP_ROWS, 256>>>(Wm2, bm2, out);
}

// round 13
// speedup vs baseline: 1.2371x; 1.0519x over previous
#include <cuda_runtime.h>
#include <cuda_fp16.h>
#include <math.h>
#include <stdint.h>

// ---------------- problem constants (fixed by dataset) ----------------
#define NODES 50000
#define NEDGE 600000
#define ETOT  (NEDGE + NODES)   // edges + self loops
#define FIN   256
#define HID   128
#define NCLS  20
#define NEG_SLOPE 0.2f

#define SCAN_BLK 1024
#define NTILES ((NODES + SCAN_BLK - 1) / SCAN_BLK)   // 49

// ---------------- scratch (static device globals; referenced directly) ----
// Invariants maintained across launches (all deterministic):
//  - g_cnt is all-zero at launch entry (zero-init at load; scan_phase1 re-zeroes)
//  - g_asmax is monotone-stable under atomicMax of identical per-run values
__device__ __align__(16) float  g_h  [(size_t)NODES * HID];  // f32 GEMM out (MLP head)
__device__ __align__(16) __half g_h16[(size_t)NODES * HID];  // fp16 GEMM out (GAT layers)
__device__ __align__(16) float  g_x2 [(size_t)NODES * HID];  // aggregation outputs
__device__ __align__(16) float  g_as [NODES];
__device__ __align__(16) float  g_ad [NODES];
__device__ int g_cnt[NODES];
__device__ int g_rowptr[NODES + 1];   // LOCAL exclusive scan per 1024-tile; [NODES]=total
__device__ int g_fill[NODES];         // local cursors for fill
__device__ int g_col[ETOT];
__device__ int g_tilesum[NTILES];
__device__ int g_tileoff[NTILES];
__device__ unsigned g_asmax[2];       // order-encoded global max of g_as, per GAT layer

// ---------------- streams/events for forked graph capture (created at load) ----
struct GraphStreams {
    cudaStream_t side = nullptr;
    cudaEvent_t ev_fork = nullptr, ev_join = nullptr;
    GraphStreams() {
        cudaStreamCreateWithFlags(&side, cudaStreamNonBlocking);
        cudaEventCreateWithFlags(&ev_fork, cudaEventDisableTiming);
        cudaEventCreateWithFlags(&ev_join, cudaEventDisableTiming);
    }
};
static GraphStreams g_gs;

// ---------------- order-preserving float<->uint encoding (for atomicMax) ----
__device__ __forceinline__ unsigned enc_ord(float f) {
    unsigned u = __float_as_uint(f);
    return (u & 0x80000000u) ? ~u : (u | 0x80000000u);
}
__device__ __forceinline__ float dec_ord(unsigned k) {
    return (k & 0x80000000u) ? __uint_as_float(k & 0x7fffffffu)
                             : __uint_as_float(~k);
}

// ---------------- cp.async helpers ----------------
__device__ __forceinline__ void cp_async16(uint32_t dst, const void* src, int src_bytes) {
    asm volatile("cp.async.cg.shared.global [%0], [%1], 16, %2;"
                 :: "r"(dst), "l"(src), "r"(src_bytes));
}
__device__ __forceinline__ void cp_commit() { asm volatile("cp.async.commit_group;"); }
template <int N>
__device__ __forceinline__ void cp_wait() { asm volatile("cp.async.wait_group %0;" :: "n"(N)); }

__device__ __forceinline__ uint32_t f2tf32(float x) {
    uint32_t r;
    asm("cvt.rna.tf32.f32 %0, %1;" : "=r"(r) : "f"(x));
    return r;
}
__device__ __forceinline__ void mma_tf32(float* d, const uint32_t* a, const uint32_t* b) {
    asm volatile(
        "mma.sync.aligned.m16n8k8.row.col.f32.tf32.tf32.f32 "
        "{%0,%1,%2,%3}, {%4,%5,%6,%7}, {%8,%9}, {%0,%1,%2,%3};"
        : "+f"(d[0]), "+f"(d[1]), "+f"(d[2]), "+f"(d[3])
        : "r"(a[0]), "r"(a[1]), "r"(a[2]), "r"(a[3]), "r"(b[0]), "r"(b[1]));
}

// per-block dtype probe: int64 layout => odd 32-bit words of first 4 ids all zero
__device__ __forceinline__ int probe_is64_block(const void* ei) {
    __shared__ int s_is64;
    if (threadIdx.x == 0) {
        const unsigned* p = (const unsigned*)ei;
        s_is64 = ((p[1] | p[3] | p[5] | p[7]) == 0u) ? 1 : 0;
    }
    __syncthreads();
    return s_is64;
}

__device__ __forceinline__ int load_edge_i(const void* ei, long long idx, int is64) {
    int v;
    if (is64) v = (int)((const long long*)ei)[idx];
    else      v = ((const int*)ei)[idx];
    return (v < 0) ? 0 : (v >= NODES ? NODES - 1 : v);
}

// ---------------- CSR build ----------------
__global__ void count_edges_k(const void* __restrict__ ei) {
    int is64 = probe_is64_block(ei);
    int e = blockIdx.x * blockDim.x + threadIdx.x;
    if (e >= ETOT) return;
    int dst = (e < NEDGE) ? load_edge_i(ei, (long long)NEDGE + e, is64) : (e - NEDGE);
    atomicAdd(&g_cnt[dst], 1);
}

// local exclusive scan per 1024-tile; zero g_cnt after reading; init local cursors
__global__ void scan_phase1_k() {
    __shared__ int sh[SCAN_BLK];
    int t = threadIdx.x;
    int i = blockIdx.x * SCAN_BLK + t;
    int v = (i < NODES) ? g_cnt[i] : 0;
    sh[t] = v;
    __syncthreads();
    for (int off = 1; off < SCAN_BLK; off <<= 1) {
        int x = 0;
        if (t >= off) x = sh[t - off];
        __syncthreads();
        sh[t] += x;
        __syncthreads();
    }
    if (i < NODES) {
        int loc = sh[t] - v;       // local exclusive
        g_rowptr[i] = loc;
        g_fill[i]   = loc;
        g_cnt[i]    = 0;           // restore all-zero invariant for next launch
    }
    if (t == SCAN_BLK - 1) g_tilesum[blockIdx.x] = sh[t];
}

__global__ void scan_phase2_k() {
    __shared__ int sh[64];
    int t = threadIdx.x;
    int v = (t < NTILES) ? g_tilesum[t] : 0;
    sh[t] = v;
    __syncthreads();
    for (int off = 1; off < 64; off <<= 1) {
        int x = 0;
        if (t >= off) x = sh[t - off];
        __syncthreads();
        sh[t] += x;
        __syncthreads();
    }
    if (t < NTILES) g_tileoff[t] = sh[t] - v;
    if (t == 63) g_rowptr[NODES] = sh[63];   // absolute total
}

__global__ void fill_edges_k(const void* __restrict__ ei) {
    int is64 = probe_is64_block(ei);
    int e = blockIdx.x * blockDim.x + threadIdx.x;
    if (e >= ETOT) return;
    int src, dst;
    if (e < NEDGE) {
        src = load_edge_i(ei, e, is64);
        dst = load_edge_i(ei, (long long)NEDGE + e, is64);
    } else {
        src = dst = e - NEDGE;
    }
    int p = atomicAdd(&g_fill[dst], 1) + g_tileoff[dst >> 10];
    g_col[p] = src;
}

// ---------------- TF32 tensor-core GEMM (+ fused attention dots + asmax) -------
#define ASTR 20
#define BSTR 136

template <bool A_EXT, bool BIAS, bool RELU, bool DOTS, bool H16>
__global__ __launch_bounds__(256, 2)
void gemm_tf32_k(const float* __restrict__ Ap, const float* __restrict__ B,
                 const float* __restrict__ bias,
                 const float* __restrict__ a_src, const float* __restrict__ a_dst,
                 int M, int K, int layer) {
    const int BM = 128, BN = 128, BK = 16;
    const float* A = A_EXT ? Ap : (const float*)g_x2;

    __shared__ float As[2][BM][ASTR];
    __shared__ float Bs[2][BK][BSTR];
    __shared__ float sh_s[BM];
    __shared__ float sh_d[BM];

    const int tid  = threadIdx.x;
    const int lane = tid & 31;
    const int wid  = tid >> 5;
    const int wm   = (wid >> 2) * 64;
    const int wn   = (wid & 3) * 32;
    const int gid  = lane >> 2;
    const int tig  = lane & 3;
    const int block_row = blockIdx.x * BM;

    const int a_row  = tid / 4;
    const int a_col4 = tid % 4;
    const int b_row  = tid / 32;
    const int b_col4 = tid % 32;

    if (DOTS && tid < BM) { sh_s[tid] = 0.f; sh_d[tid] = 0.f; }

    float acc[4][4][4];
    #pragma unroll
    for (int mt = 0; mt < 4; mt++)
        #pragma unroll
        for (int nt = 0; nt < 4; nt++)
            #pragma unroll
            for (int r = 0; r < 4; r++) acc[mt][nt][r] = 0.f;

    auto load_tile = [&](int k0, int s) {
        #pragma unroll
        for (int half = 0; half < 2; half++) {
            int r = a_row + half * 64;
            int grow = block_row + r;
            const float* src = A + (size_t)grow * K + k0 + a_col4 * 4;
            uint32_t dst = (uint32_t)__cvta_generic_to_shared(&As[s][r][a_col4 * 4]);
            cp_async16(dst, src, (grow < M) ? 16 : 0);
        }
        #pragma unroll
        for (int half = 0; half < 2; half++) {
            int r = b_row + half * 8;
            const float* src = B + (size_t)(k0 + r) * BN + b_col4 * 4;
            uint32_t dst = (uint32_t)__cvta_generic_to_shared(&Bs[s][r][b_col4 * 4]);
            cp_async16(dst, src, 16);
        }
    };

    load_tile(0, 0);
    cp_commit();

    int buf = 0;
    for (int k0 = 0; k0 < K; k0 += BK) {
        if (k0 + BK < K) load_tile(k0 + BK, buf ^ 1);
        cp_commit();
        cp_wait<1>();
        __syncthreads();

        #pragma unroll
        for (int ks = 0; ks < BK; ks += 8) {
            uint32_t afr[4][4];
            #pragma unroll
            for (int mt = 0; mt < 4; mt++) {
                int r = wm + mt * 16;
                afr[mt][0] = f2tf32(As[buf][r + gid     ][ks + tig    ]);
                afr[mt][1] = f2tf32(As[buf][r + gid + 8 ][ks + tig    ]);
                afr[mt][2] = f2tf32(As[buf][r + gid     ][ks + tig + 4]);
                afr[mt][3] = f2tf32(As[buf][r + gid + 8 ][ks + tig + 4]);
            }
            uint32_t bfr[4][2];
            #pragma unroll
            for (int nt = 0; nt < 4; nt++) {
                int c = wn + nt * 8 + gid;
                bfr[nt][0] = f2tf32(Bs[buf][ks + tig    ][c]);
                bfr[nt][1] = f2tf32(Bs[buf][ks + tig + 4][c]);
            }
            #pragma unroll
            for (int mt = 0; mt < 4; mt++)
                #pragma unroll
                for (int nt = 0; nt < 4; nt++)
                    mma_tf32(acc[mt][nt], afr[mt], bfr[nt]);
        }
        __syncthreads();
        buf ^= 1;
    }
    cp_wait<0>();

    float vs[4][2], vd[4][2];
    if (DOTS) {
        #pragma unroll
        for (int nt = 0; nt < 4; nt++) {
            int col = wn + nt * 8 + 2 * tig;
            vs[nt][0] = a_src[col];     vs[nt][1] = a_src[col + 1];
            vd[nt][0] = a_dst[col];     vd[nt][1] = a_dst[col + 1];
        }
    }

    #pragma unroll
    for (int mt = 0; mt < 4; mt++) {
        #pragma unroll
        for (int half = 0; half < 2; half++) {
            int rloc = wm + mt * 16 + gid + half * 8;
            int grow = block_row + rloc;
            if (grow >= M) continue;
            float ps = 0.f, pd = 0.f;
            #pragma unroll
            for (int nt = 0; nt < 4; nt++) {
                int col = wn + nt * 8 + 2 * tig;
                float v0 = acc[mt][nt][2 * half + 0];
                float v1 = acc[mt][nt][2 * half + 1];
                if (BIAS) { v0 += bias[col]; v1 += bias[col + 1]; }
                if (RELU) { v0 = fmaxf(v0, 0.f); v1 = fmaxf(v1, 0.f); }
                if (DOTS) {
                    ps = fmaf(v0, vs[nt][0], fmaf(v1, vs[nt][1], ps));
                    pd = fmaf(v0, vd[nt][0], fmaf(v1, vd[nt][1], pd));
                }
                if (H16) {
                    __half2 hv = __floats2half2_rn(v0, v1);
                    *reinterpret_cast<__half2*>(g_h16 + (size_t)grow * BN + col) = hv;
                } else {
                    float2* dst = reinterpret_cast<float2*>(g_h + (size_t)grow * BN + col);
                    *dst = make_float2(v0, v1);
                }
            }
            if (DOTS) {
                atomicAdd(&sh_s[rloc], ps);
                atomicAdd(&sh_d[rloc], pd);
            }
        }
    }

    if (DOTS) {
        __syncthreads();
        if (tid < BM) {
            int grow = block_row + tid;
            float sv = -INFINITY;
            if (grow < M) {
                sv = sh_s[tid];
                g_as[grow] = sv;
                g_ad[grow] = sh_d[tid];
            }
            #pragma unroll
            for (int o = 16; o; o >>= 1)
                sv = fmaxf(sv, __shfl_xor_sync(0xffffffffu, sv, o));
            if ((tid & 31) == 0)
                atomicMax(&g_asmax[layer], enc_ord(sv));
        }
    }
}

// ---------------- GAT aggregation: warp/node, single pass w/ global-max bound ----
template <bool RELU>
__global__ void gat_aggregate_k(const float* __restrict__ bias, int layer) {
    int node = blockIdx.x * (blockDim.x >> 5) + (threadIdx.x >> 5);
    if (node >= NODES) return;
    int lane = threadIdx.x & 31;
    int beg = g_rowptr[node] + g_tileoff[node >> 10];
    int end;
    if (node + 1 < NODES) end = g_rowptr[node + 1] + g_tileoff[(node + 1) >> 10];
    else                  end = g_rowptr[NODES];
    float adn = g_ad[node];

    float m = dec_ord(g_asmax[layer]) + adn;
    m = m > 0.f ? m : NEG_SLOPE * m;

    float4 acc = make_float4(0.f, 0.f, 0.f, 0.f);
    float denom = 0.f;
    #pragma unroll 2
    for (int e = beg; e < end; e++) {
        int s = g_col[e];
        float l = g_as[s] + adn;
        l = l > 0.f ? l : NEG_SLOPE * l;
        float w = __expf(l - m);
        denom += w;
        uint2 raw = reinterpret_cast<const uint2*>(g_h16 + (size_t)s * HID)[lane];
        __half2 p0 = *reinterpret_cast<__half2*>(&raw.x);
        __half2 p1 = *reinterpret_cast<__half2*>(&raw.y);
        float2 f0 = __half22float2(p0);
        float2 f1 = __half22float2(p1);
        acc.x = fmaf(w, f0.x, acc.x);
        acc.y = fmaf(w, f0.y, acc.y);
        acc.z = fmaf(w, f1.x, acc.z);
        acc.w = fmaf(w, f1.y, acc.w);
    }
    float inv = 1.f / denom;
    float4 b4 = reinterpret_cast<const float4*>(bias)[lane];
    float4 o4;
    o4.x = acc.x * inv + b4.x;
    o4.y = acc.y * inv + b4.y;
    o4.z = acc.z * inv + b4.z;
    o4.w = acc.w * inv + b4.w;
    if (RELU) {
        o4.x = fmaxf(o4.x, 0.f); o4.y = fmaxf(o4.y, 0.f);
        o4.z = fmaxf(o4.z, 0.f); o4.w = fmaxf(o4.w, 0.f);
    }
    reinterpret_cast<float4*>(g_x2 + (size_t)node * HID)[lane] = o4;
}

// ---------------- final: out = sigmoid(g_h @ Wm2 + bm2), vectorized ----------------
#define MLP_ROWS 64
__global__ __launch_bounds__(256)
void mlp_out_k(const float* __restrict__ W, const float* __restrict__ b,
               float* __restrict__ out) {
    __shared__ float Wst[NCLS][HID + 4];
    __shared__ float bs[NCLS];
    __shared__ __align__(16) float hs[MLP_ROWS][HID];

    int tid = threadIdx.x;
    for (int i = tid; i < HID * NCLS; i += blockDim.x)
        Wst[i % NCLS][i / NCLS] = W[i];
    if (tid < NCLS) bs[tid] = b[tid];

    int row0 = blockIdx.x * MLP_ROWS;
    const float4* src = reinterpret_cast<const float4*>(g_h + (size_t)row0 * HID);
    float4* dst4 = reinterpret_cast<float4*>(&hs[0][0]);
    int n4 = min(MLP_ROWS, NODES - row0) * (HID / 4);
    for (int i = tid; i < n4; i += blockDim.x) dst4[i] = src[i];
    __syncthreads();

    int nout = min(MLP_ROWS, NODES - row0) * NCLS;
    for (int o = tid; o < nout; o += blockDim.x) {
        int rl = o / NCLS, c = o % NCLS;
        const float4* zr = reinterpret_cast<const float4*>(&hs[rl][0]);
        const float4* wc = reinterpret_cast<const float4*>(&Wst[c][0]);
        float acc = bs[c];
        #pragma unroll
        for (int k = 0; k < HID / 4; k++) {
            float4 z = zr[k];
            float4 w = wc[k];
            acc = fmaf(z.x, w.x, acc);
            acc = fmaf(z.y, w.y, acc);
            acc = fmaf(z.z, w.z, acc);
            acc = fmaf(z.w, w.w, acc);
        }
        out[(size_t)(row0 + rl) * NCLS + c] = 1.f / (1.f + __expf(-acc));
    }
}

// ---------------- launch ----------------
extern "C" void kernel_launch(void* const* d_in, const int* in_sizes, int n_in,
                              void* d_out, int out_size) {
    const float* x    = (const float*)d_in[0];
    const void*  ei   = d_in[1];
    const float* W1   = (const float*)d_in[2];
    const float* as1  = (const float*)d_in[3];
    const float* ad1  = (const float*)d_in[4];
    const float* b1   = (const float*)d_in[5];
    const float* W2   = (const float*)d_in[6];
    const float* as2  = (const float*)d_in[7];
    const float* ad2  = (const float*)d_in[8];
    const float* b2   = (const float*)d_in[9];
    const float* Wm1  = (const float*)d_in[10];
    const float* bm1  = (const float*)d_in[11];
    const float* Wm2  = (const float*)d_in[12];
    const float* bm2  = (const float*)d_in[13];
    float*       out  = (float*)d_out;

    const int gemm_grid  = (NODES + 127) / 128;
    const int warps_grid = (NODES + 7) / 8;
    const int edge_grid  = (ETOT + 255) / 256;

    // --- fork: CSR build on side stream, GEMM1 on main stream (independent) ---
    cudaEventRecord(g_gs.ev_fork, 0);
    cudaStreamWaitEvent(g_gs.side, g_gs.ev_fork, 0);

    count_edges_k<<<edge_grid, 256, 0, g_gs.side>>>(ei);
    scan_phase1_k<<<NTILES, SCAN_BLK, 0, g_gs.side>>>();
    scan_phase2_k<<<1, 64, 0, g_gs.side>>>();
    fill_edges_k<<<edge_grid, 256, 0, g_gs.side>>>(ei);
    cudaEventRecord(g_gs.ev_join, g_gs.side);

    // main stream: GAT layer 1 GEMM (+ fused dots/asmax, fp16 h)
    gemm_tf32_k<true, false, false, true, true><<<gemm_grid, 256>>>(x, W1, nullptr, as1, ad1, NODES, FIN, 0);

    // join: aggregate needs CSR + GEMM1 outputs
    cudaStreamWaitEvent(0, g_gs.ev_join, 0);
    gat_aggregate_k<true><<<warps_grid, 256>>>(b1, 0);

    // --- GAT layer 2 (GEMM + fused dots/asmax, fp16 h) ---
    gemm_tf32_k<false, false, false, true, true><<<gemm_grid, 256>>>(nullptr, W2, nullptr, as2, ad2, NODES, HID, 1);
    gat_aggregate_k<false><<<warps_grid, 256>>>(b2, 1);

    // --- MLP head (f32 h) ---
    gemm_tf32_k<false, true, true, false, false><<<gemm_grid, 256>>>(nullptr, Wm1, bm1, nullptr, nullptr, NODES, HID, 0);
    mlp_out_k<<<(NODES + MLP_ROWS - 1) / MLP_ROWS, 256>>>(Wm2, bm2, out);
}